// round 2
// baseline (speedup 1.0000x reference)
#include <cuda_runtime.h>

#define NCTA 128
#define NTHR 256
#define Bk 128
#define Sk 1024
#define Fk 8
#define Hk 512
#define Ok 8
#define KC 16
#define HPAD 68

typedef unsigned long long ull;

// persistent device state (zero-initialized at module load; re-zeroed each launch)
__device__ float g_h0[2][Bk * Hk];
__device__ float g_h1[2][Bk * Hk];
__device__ unsigned g_count;   // net-zero after each barrier (sub-based reset)
__device__ unsigned g_epoch;   // monotonic across barriers and graph replays

// ---------------- packed f32x2 helpers ----------------
__device__ __forceinline__ ull pack2(float a, float b) {
    ull r; asm("mov.b64 %0, {%1, %2};" : "=l"(r) : "f"(a), "f"(b)); return r;
}
__device__ __forceinline__ void fma2(ull& d, ull a, ull b) {
    asm("fma.rn.f32x2 %0, %1, %2, %0;" : "+l"(d) : "l"(a), "l"(b));
}
__device__ __forceinline__ float2 unp(ull v) {
    float2 r; asm("mov.b64 {%0, %1}, %2;" : "=f"(r.x), "=f"(r.y) : "l"(v)); return r;
}
__device__ __forceinline__ float sigf(float x) {
    return __fdividef(1.0f, 1.0f + __expf(-x));
}
__device__ __forceinline__ float tanh_f(float x) {
    return 2.0f * sigf(2.0f * x) - 1.0f;
}

// ---------------- software grid barrier ----------------
// Requires all NCTA CTAs resident (guaranteed: 128 CTAs, 1/SM by smem, 148 SMs).
__device__ __forceinline__ void grid_sync() {
    __syncthreads();
    if (threadIdx.x == 0) {
        __threadfence();
        unsigned e = *(volatile unsigned*)&g_epoch;  // read BEFORE arriving: safe
        unsigned old = atomicAdd(&g_count, 1u);
        if (old == NCTA - 1u) {
            atomicSub(&g_count, (unsigned)NCTA);     // commutes with next-barrier arrivals
            __threadfence();
            atomicAdd(&g_epoch, 1u);
        } else {
            while (*(volatile unsigned*)&g_epoch == e) { }
            __threadfence();
        }
    }
    __syncthreads();
}

// ---------------- GEMM over one k-half ----------------
// All 256 threads call this (both halves), so internal __syncthreads align.
// hsrc_base: global h source for THIS half, already offset to (bbase row, k-half col).
// Ws: smem weight rows base for THIS half ([k][32] layout, k relative).
// hb: this half's hbuf base (2 buffers of [KC][HPAD]).
__device__ __forceinline__ void gemm_half_run(
    const float* __restrict__ hsrc_base,
    const float* __restrict__ Ws,
    float* hb, int nchunk, int u, ull acc[4][2])
{
    const int cg = u & 7, rg = u >> 3;
    const int cb = cg * 4, rb = rg * 4;
    const int v0 = u, v1 = u + 128;
    const int b0i = v0 >> 2, kq0 = (v0 & 3) * 4;
    const int b1i = v1 >> 2, kq1 = (v1 & 3) * 4;

    float4 p0 = __ldcg((const float4*)(hsrc_base + b0i * Hk + kq0));
    float4 p1 = __ldcg((const float4*)(hsrc_base + b1i * Hk + kq1));
    // store chunk 0 into buf 0
    {
        float* d = hb;
        d[(kq0 + 0) * HPAD + b0i] = p0.x; d[(kq0 + 1) * HPAD + b0i] = p0.y;
        d[(kq0 + 2) * HPAD + b0i] = p0.z; d[(kq0 + 3) * HPAD + b0i] = p0.w;
        d[(kq1 + 0) * HPAD + b1i] = p1.x; d[(kq1 + 1) * HPAD + b1i] = p1.y;
        d[(kq1 + 2) * HPAD + b1i] = p1.z; d[(kq1 + 3) * HPAD + b1i] = p1.w;
    }
    __syncthreads();

    for (int ch = 0; ch < nchunk; ch++) {
        const int cur = ch & 1;
        if (ch + 1 < nchunk) {  // prefetch next chunk into registers
            p0 = __ldcg((const float4*)(hsrc_base + b0i * Hk + (ch + 1) * KC + kq0));
            p1 = __ldcg((const float4*)(hsrc_base + b1i * Hk + (ch + 1) * KC + kq1));
        }
        const float* hbc = hb + cur * (KC * HPAD);
        const float* W = Ws + ch * KC * 32;
#pragma unroll
        for (int k = 0; k < KC; k++) {
            ull w01 = *(const ull*)(W + k * 32 + cb);
            ull w23 = *(const ull*)(W + k * 32 + cb + 2);
            float4 h4 = *(const float4*)(hbc + k * HPAD + rb);
            ull hp;
            hp = pack2(h4.x, h4.x); fma2(acc[0][0], hp, w01); fma2(acc[0][1], hp, w23);
            hp = pack2(h4.y, h4.y); fma2(acc[1][0], hp, w01); fma2(acc[1][1], hp, w23);
            hp = pack2(h4.z, h4.z); fma2(acc[2][0], hp, w01); fma2(acc[2][1], hp, w23);
            hp = pack2(h4.w, h4.w); fma2(acc[3][0], hp, w01); fma2(acc[3][1], hp, w23);
        }
        if (ch + 1 < nchunk) {  // store prefetched chunk into the other buffer
            float* d = hb + (cur ^ 1) * (KC * HPAD);
            d[(kq0 + 0) * HPAD + b0i] = p0.x; d[(kq0 + 1) * HPAD + b0i] = p0.y;
            d[(kq0 + 2) * HPAD + b0i] = p0.z; d[(kq0 + 3) * HPAD + b0i] = p0.w;
            d[(kq1 + 0) * HPAD + b1i] = p1.x; d[(kq1 + 1) * HPAD + b1i] = p1.y;
            d[(kq1 + 2) * HPAD + b1i] = p1.z; d[(kq1 + 3) * HPAD + b1i] = p1.w;
        }
        __syncthreads();
    }
}

// combine k-split halves and write the [64][32] gate block to gbuf
__device__ __forceinline__ void combine_halves(
    ull acc[4][2], float* gbuf, float* sgacc, int half, int u)
{
    const int cg = u & 7, rg = u >> 3;
    const int cb = cg * 4, rb = rg * 4;
    if (half == 1) {
        float* sg = sgacc + u * 16;
#pragma unroll
        for (int i = 0; i < 4; i++) {
            float2 a = unp(acc[i][0]), b = unp(acc[i][1]);
            sg[i * 4 + 0] = a.x; sg[i * 4 + 1] = a.y;
            sg[i * 4 + 2] = b.x; sg[i * 4 + 3] = b.y;
        }
    }
    __syncthreads();
    if (half == 0) {
        const float* sg = sgacc + u * 16;
#pragma unroll
        for (int i = 0; i < 4; i++) {
            float2 a = unp(acc[i][0]), b = unp(acc[i][1]);
            gbuf[(rb + i) * 33 + cb + 0] = a.x + sg[i * 4 + 0];
            gbuf[(rb + i) * 33 + cb + 1] = a.y + sg[i * 4 + 1];
            gbuf[(rb + i) * 33 + cb + 2] = b.x + sg[i * 4 + 2];
            gbuf[(rb + i) * 33 + cb + 3] = b.y + sg[i * 4 + 3];
        }
    }
    __syncthreads();
}

// smem: W0s 16384 | W1s 32768 | Wih0s 256 | b0s 32 | b1s 32 | hbuf 4352 | gbuf 2112 | sgacc 2048
#define SMEM_FLOATS (16384 + 32768 + 256 + 32 + 32 + 4352 + 2112 + 2048)
#define SMEM_BYTES (SMEM_FLOATS * 4)

extern __shared__ float smem[];

__global__ void __launch_bounds__(NTHR, 1) lstm2_kernel(
    const float* __restrict__ x,
    const float* __restrict__ Wih0, const float* __restrict__ Whh0,
    const float* __restrict__ bih0, const float* __restrict__ bhh0,
    const float* __restrict__ Wih1, const float* __restrict__ Whh1,
    const float* __restrict__ bih1, const float* __restrict__ bhh1,
    const float* __restrict__ Wfc, const float* __restrict__ bfc,
    float* __restrict__ out)
{
    float* W0s   = smem;                    // [512][32]  layer0 W_hh slice
    float* W1s   = W0s + 512 * 32;          // [1024][32] layer1 [W_ih1; W_hh1] slice
    float* Wih0s = W1s + 1024 * 32;         // [32][8]
    float* b0s   = Wih0s + 32 * 8;          // [32]
    float* b1s   = b0s + 32;                // [32]
    float* hbufA = b1s + 32;                // [2 halves][2 bufs][KC][HPAD]
    float* gbuf  = hbufA + 2 * 2 * KC * HPAD; // [64][33]
    float* sgacc = gbuf + 64 * 33;          // [128][16]

    const int t = threadIdx.x;
    const int cta = blockIdx.x;
    const int dg = cta >> 1;        // hidden-dim group: dims dg*8 .. dg*8+7
    const int bh = cta & 1;         // batch half
    const int bbase = bh * 64;
    const int half = t >> 7;        // k-split half
    const int u = t & 127;

    // ---- load weight slices into smem (coalesced along k) ----
    for (int c = 0; c < 32; c++) {
        const int grow = ((c >> 3) * Hk) + dg * 8 + (c & 7);  // gate-major global row
        const float* s0 = Whh0 + (size_t)grow * Hk;
        const float* s1 = Wih1 + (size_t)grow * Hk;
        const float* s2 = Whh1 + (size_t)grow * Hk;
        for (int k = t; k < Hk; k += NTHR) {
            W0s[k * 32 + c] = s0[k];
            W1s[k * 32 + c] = s1[k];
            W1s[(Hk + k) * 32 + c] = s2[k];
        }
    }
    {
        const int c = t >> 3, k = t & 7;   // t in [0,256): c in [0,32)
        const int grow = ((c >> 3) * Hk) + dg * 8 + (c & 7);
        Wih0s[c * 8 + k] = Wih0[grow * Fk + k];
    }
    if (t < 32) {
        const int grow = ((t >> 3) * Hk) + dg * 8 + (t & 7);
        b0s[t] = bih0[grow] + bhh0[grow];
        b1s[t] = bih1[grow] + bhh1[grow];
    }
    // zero both parities of h state
    for (int i = cta * NTHR + t; i < 2 * Bk * Hk; i += NCTA * NTHR) {
        ((float*)g_h0)[i] = 0.0f;
        ((float*)g_h1)[i] = 0.0f;
    }
    grid_sync();  // barrier 0: weights local (syncthreads inside), state zeroed globally

    float c0a = 0.f, c0b = 0.f, c1a = 0.f, c1b = 0.f;  // cell state, 2 items/thread/layer

    for (int step = 0; step < Sk; step++) {
        const int p = step & 1;
        const float* h0_old = g_h0[p];
        float*       h0_new = g_h0[1 - p];
        const float* h1_old = g_h1[p];
        float*       h1_new = g_h1[1 - p];

        // ================= phase A: layer-0 gates =================
        {
            ull acc[4][2];
#pragma unroll
            for (int i = 0; i < 4; i++) { acc[i][0] = 0ull; acc[i][1] = 0ull; }
            const float* hsrc = h0_old + (size_t)bbase * Hk + half * 256;
            const float* Ws = W0s + half * 256 * 32;
            float* hb = hbufA + half * (2 * KC * HPAD);
            gemm_half_run(hsrc, Ws, hb, 256 / KC, u, acc);
            combine_halves(acc, gbuf, sgacc, half, u);
        }
        // activation layer 0 (all 256 threads, items t and t+256)
        {
            float* creg[2] = { &c0a, &c0b };
            int mm = t;
#pragma unroll
            for (int it = 0; it < 2; it++, mm += 256) {
                const int bl = mm >> 3, dim = mm & 7;
                const int bg = bbase + bl;
                const float4 xa = *(const float4*)(x + ((size_t)bg * Sk + step) * Fk);
                const float4 xb = *(const float4*)(x + ((size_t)bg * Sk + step) * Fk + 4);
                float gate[4];
#pragma unroll
                for (int g = 0; g < 4; g++) {
                    const int col = g * 8 + dim;
                    const float* wv = Wih0s + col * 8;
                    float s = gbuf[bl * 33 + col] + b0s[col];
                    s += xa.x * wv[0] + xa.y * wv[1] + xa.z * wv[2] + xa.w * wv[3];
                    s += xb.x * wv[4] + xb.y * wv[5] + xb.z * wv[6] + xb.w * wv[7];
                    gate[g] = s;
                }
                const float ig = sigf(gate[0]);
                const float fg = sigf(gate[1]);
                const float gg = tanh_f(gate[2]);
                const float og = sigf(gate[3]);
                const float cn = fg * (*creg[it]) + ig * gg;
                *creg[it] = cn;
                h0_new[(size_t)bg * Hk + dg * 8 + dim] = og * tanh_f(cn);
            }
        }
        grid_sync();  // barrier 1: h0_new visible everywhere

        // ================= phase B: layer-1 gates =================
        {
            ull acc[4][2];
#pragma unroll
            for (int i = 0; i < 4; i++) { acc[i][0] = 0ull; acc[i][1] = 0ull; }
            const float* hsrc = (half == 0)
                ? (h0_new + (size_t)bbase * Hk)     // k 0..511 : W_ih1 @ h0_new
                : (h1_old + (size_t)bbase * Hk);    // k 512..1023 : W_hh1 @ h1_old
            const float* Ws = W1s + half * 512 * 32;
            float* hb = hbufA + half * (2 * KC * HPAD);
            gemm_half_run(hsrc, Ws, hb, 512 / KC, u, acc);
            combine_halves(acc, gbuf, sgacc, half, u);
        }
        // activation layer 1
        {
            float* creg[2] = { &c1a, &c1b };
            int mm = t;
#pragma unroll
            for (int it = 0; it < 2; it++, mm += 256) {
                const int bl = mm >> 3, dim = mm & 7;
                const int bg = bbase + bl;
                float gate[4];
#pragma unroll
                for (int g = 0; g < 4; g++) {
                    const int col = g * 8 + dim;
                    gate[g] = gbuf[bl * 33 + col] + b1s[col];
                }
                const float ig = sigf(gate[0]);
                const float fg = sigf(gate[1]);
                const float gg = tanh_f(gate[2]);
                const float og = sigf(gate[3]);
                const float cn = fg * (*creg[it]) + ig * gg;
                *creg[it] = cn;
                h1_new[(size_t)bg * Hk + dg * 8 + dim] = og * tanh_f(cn);
            }
        }
        grid_sync();  // barrier 2: h1_new visible everywhere

        // ============ FC for this step (CTAs 0..15, overlaps next step) ============
        if (cta < 16) {
            const int o = cta >> 1;
            const int bh2 = cta & 1;
            const int bl = t >> 2, q = t & 3;
            const int bg = bh2 * 64 + bl;
            const float* hrow = h1_new + (size_t)bg * Hk;
            const float* wrow = Wfc + (size_t)o * Hk;
            float s = 0.f;
            const int k0 = q * 128;
#pragma unroll 8
            for (int k = 0; k < 128; k++) {
                s = fmaf(__ldcg(hrow + k0 + k), __ldg(wrow + k0 + k), s);
            }
            s += __shfl_xor_sync(0xffffffffu, s, 1);
            s += __shfl_xor_sync(0xffffffffu, s, 2);
            if (q == 0) {
                out[((size_t)bg * Sk + step) * Ok + o] = s + __ldg(bfc + o);
            }
        }
    }
}

extern "C" void kernel_launch(void* const* d_in, const int* in_sizes, int n_in,
                              void* d_out, int out_size) {
    const float* x    = (const float*)d_in[0];
    const float* Wih0 = (const float*)d_in[1];
    const float* Whh0 = (const float*)d_in[2];
    const float* bih0 = (const float*)d_in[3];
    const float* bhh0 = (const float*)d_in[4];
    const float* Wih1 = (const float*)d_in[5];
    const float* Whh1 = (const float*)d_in[6];
    const float* bih1 = (const float*)d_in[7];
    const float* bhh1 = (const float*)d_in[8];
    const float* Wfc  = (const float*)d_in[9];
    const float* bfc  = (const float*)d_in[10];
    float* out = (float*)d_out;

    cudaFuncSetAttribute(lstm2_kernel,
                         cudaFuncAttributeMaxDynamicSharedMemorySize, SMEM_BYTES);
    lstm2_kernel<<<NCTA, NTHR, SMEM_BYTES>>>(
        x, Wih0, Whh0, bih0, bhh0, Wih1, Whh1, bih1, bhh1, Wfc, bfc, out);
}

// round 3
// speedup vs baseline: 1.3519x; 1.3519x over previous
#include <cuda_runtime.h>

#define NCTA 128
#define NTHR 512
#define Bk 128
#define Sk 1024
#define Fk 8
#define Hk 512
#define Ok 8
#define KC 16
#define HPAD 68

typedef unsigned long long ull;

// persistent device state
__device__ float g_h0[2][Bk * Hk];
__device__ float g_h1[2][Bk * Hk];
__device__ unsigned g_count;   // net-zero after each barrier (sub-based reset)
__device__ unsigned g_epoch;   // monotonic across barriers and graph replays

// ---------------- packed f32x2 helpers ----------------
__device__ __forceinline__ ull pack2(float a, float b) {
    ull r; asm("mov.b64 %0, {%1, %2};" : "=l"(r) : "f"(a), "f"(b)); return r;
}
__device__ __forceinline__ void fma2(ull& d, ull a, ull b) {
    asm("fma.rn.f32x2 %0, %1, %2, %0;" : "+l"(d) : "l"(a), "l"(b));
}
__device__ __forceinline__ float2 unp(ull v) {
    float2 r; asm("mov.b64 {%0, %1}, %2;" : "=f"(r.x), "=f"(r.y) : "l"(v)); return r;
}
__device__ __forceinline__ float sigf(float x) {
    return __fdividef(1.0f, 1.0f + __expf(-x));
}
__device__ __forceinline__ float tanh_f(float x) {
    return 2.0f * sigf(2.0f * x) - 1.0f;
}

// ---------------- software grid barrier ----------------
__device__ __forceinline__ void grid_sync() {
    __syncthreads();
    if (threadIdx.x == 0) {
        __threadfence();
        unsigned e = *(volatile unsigned*)&g_epoch;  // read BEFORE arriving
        unsigned old = atomicAdd(&g_count, 1u);
        if (old == NCTA - 1u) {
            atomicSub(&g_count, (unsigned)NCTA);
            __threadfence();
            atomicAdd(&g_epoch, 1u);
        } else {
            while (*(volatile unsigned*)&g_epoch == e) { }
            __threadfence();
        }
    }
    __syncthreads();
}

// ---------------- GEMM over one k-split (single-buffered hbuf) ----------------
// All 512 threads call this; identical nchunk for every split -> syncs align.
// hsrc: global h source for THIS split (already offset to (bbase, k-offset)).
// Ws:   smem weight rows for THIS split ([k][32], k relative).
// hb:   this split's hbuf base ([KC][HPAD]).
__device__ __forceinline__ void gemm_run(
    const float* __restrict__ hsrc,
    const float* __restrict__ Ws,
    float* hb, int nchunk, int u, ull acc[4][2])
{
    const int cb = (u & 7) * 4;
    const int rb = (u >> 3) * 4;
    const int b0i = u >> 2;          // 0..31
    const int b1i = b0i + 32;        // 32..63
    const int kq = (u & 3) * 4;      // 0,4,8,12

    float4 p0 = __ldcg((const float4*)(hsrc + b0i * Hk + kq));
    float4 p1 = __ldcg((const float4*)(hsrc + b1i * Hk + kq));

    for (int ch = 0; ch < nchunk; ch++) {
        // store the prefetched chunk
        hb[(kq + 0) * HPAD + b0i] = p0.x; hb[(kq + 1) * HPAD + b0i] = p0.y;
        hb[(kq + 2) * HPAD + b0i] = p0.z; hb[(kq + 3) * HPAD + b0i] = p0.w;
        hb[(kq + 0) * HPAD + b1i] = p1.x; hb[(kq + 1) * HPAD + b1i] = p1.y;
        hb[(kq + 2) * HPAD + b1i] = p1.z; hb[(kq + 3) * HPAD + b1i] = p1.w;
        __syncthreads();
        if (ch + 1 < nchunk) {  // issue next chunk's global loads early
            p0 = __ldcg((const float4*)(hsrc + b0i * Hk + (ch + 1) * KC + kq));
            p1 = __ldcg((const float4*)(hsrc + b1i * Hk + (ch + 1) * KC + kq));
        }
        const float* W = Ws + ch * KC * 32;
#pragma unroll
        for (int k = 0; k < KC; k++) {
            ull w01 = *(const ull*)(W + k * 32 + cb);
            ull w23 = *(const ull*)(W + k * 32 + cb + 2);
            float4 h4 = *(const float4*)(hb + k * HPAD + rb);
            ull hp;
            hp = pack2(h4.x, h4.x); fma2(acc[0][0], hp, w01); fma2(acc[0][1], hp, w23);
            hp = pack2(h4.y, h4.y); fma2(acc[1][0], hp, w01); fma2(acc[1][1], hp, w23);
            hp = pack2(h4.z, h4.z); fma2(acc[2][0], hp, w01); fma2(acc[2][1], hp, w23);
            hp = pack2(h4.w, h4.w); fma2(acc[3][0], hp, w01); fma2(acc[3][1], hp, w23);
        }
        __syncthreads();  // hbuf reads done before next store
    }
}

// combine 4 k-split partials -> gbuf [64][33]
__device__ __forceinline__ void combine4(
    ull acc[4][2], float* gbuf, float* sgacc, int split, int u)
{
    const int cb = (u & 7) * 4;
    const int rb = (u >> 3) * 4;
    if (split != 0) {
        float4* sg = (float4*)(sgacc + (split - 1) * 2048 + u * 16);
#pragma unroll
        for (int i = 0; i < 4; i++) {
            float2 a = unp(acc[i][0]), b = unp(acc[i][1]);
            sg[i] = make_float4(a.x, a.y, b.x, b.y);
        }
    }
    __syncthreads();
    if (split == 0) {
        const float4* s1 = (const float4*)(sgacc + 0 * 2048 + u * 16);
        const float4* s2 = (const float4*)(sgacc + 1 * 2048 + u * 16);
        const float4* s3 = (const float4*)(sgacc + 2 * 2048 + u * 16);
#pragma unroll
        for (int i = 0; i < 4; i++) {
            float2 a = unp(acc[i][0]), b = unp(acc[i][1]);
            float4 q1 = s1[i], q2 = s2[i], q3 = s3[i];
            gbuf[(rb + i) * 33 + cb + 0] = a.x + q1.x + q2.x + q3.x;
            gbuf[(rb + i) * 33 + cb + 1] = a.y + q1.y + q2.y + q3.y;
            gbuf[(rb + i) * 33 + cb + 2] = b.x + q1.z + q2.z + q3.z;
            gbuf[(rb + i) * 33 + cb + 3] = b.y + q1.w + q2.w + q3.w;
        }
    }
    __syncthreads();
}

// smem layout (floats):
//   W0s 16384 | W1s 32768 | Wih0s 256 | b0s 32 | b1s 32 | scratch 8256
//   scratch: hbuf (4 splits x KC x HPAD = 4352)  OR  sgacc 6144 + gbuf 2112
#define SMEM_FLOATS (16384 + 32768 + 256 + 32 + 32 + 8256)
#define SMEM_BYTES (SMEM_FLOATS * 4)

extern __shared__ float smem[];

__global__ void __launch_bounds__(NTHR, 1) lstm2_kernel(
    const float* __restrict__ x,
    const float* __restrict__ Wih0, const float* __restrict__ Whh0,
    const float* __restrict__ bih0, const float* __restrict__ bhh0,
    const float* __restrict__ Wih1, const float* __restrict__ Whh1,
    const float* __restrict__ bih1, const float* __restrict__ bhh1,
    const float* __restrict__ Wfc, const float* __restrict__ bfc,
    float* __restrict__ out)
{
    float* W0s    = smem;                     // [512][32]
    float* W1s    = W0s + 512 * 32;           // [1024][32]
    float* Wih0s  = W1s + 1024 * 32;          // [32][8]
    float* b0s    = Wih0s + 256;              // [32]
    float* b1s    = b0s + 32;                 // [32]
    float* scratch = b1s + 32;
    float* hbufA  = scratch;                  // [4 splits][KC][HPAD]
    float* sgacc  = scratch;                  // [3][2048] (after hbuf dead)
    float* gbuf   = scratch + 6144;           // [64][33]

    const int t = threadIdx.x;
    const int cta = blockIdx.x;
    const int dg = cta >> 1;        // hidden-dim group: dims dg*8 .. dg*8+7
    const int bh = cta & 1;         // batch half
    const int bbase = bh * 64;
    const int split = t >> 7;       // k-split 0..3
    const int u = t & 127;

    // ---- load weight slices into smem (coalesced along k) ----
    for (int c = 0; c < 32; c++) {
        const int grow = ((c >> 3) * Hk) + dg * 8 + (c & 7);  // gate-major row
        const float* s0 = Whh0 + (size_t)grow * Hk;
        const float* s1 = Wih1 + (size_t)grow * Hk;
        const float* s2 = Whh1 + (size_t)grow * Hk;
        for (int k = t; k < Hk; k += NTHR) {
            W0s[k * 32 + c] = s0[k];
            W1s[k * 32 + c] = s1[k];
            W1s[(Hk + k) * 32 + c] = s2[k];
        }
    }
    if (t < 256) {
        const int c = t >> 3, k = t & 7;
        const int grow = ((c >> 3) * Hk) + dg * 8 + (c & 7);
        Wih0s[c * 8 + k] = Wih0[grow * Fk + k];
    }
    if (t < 32) {
        const int grow = ((t >> 3) * Hk) + dg * 8 + (t & 7);
        b0s[t] = bih0[grow] + bhh0[grow];
        b1s[t] = bih1[grow] + bhh1[grow];
    }
    // zero both parities of h state
    for (int i = cta * NTHR + t; i < 2 * Bk * Hk; i += NCTA * NTHR) {
        ((float*)g_h0)[i] = 0.0f;
        ((float*)g_h1)[i] = 0.0f;
    }
    grid_sync();

    float c0 = 0.f, c1 = 0.f;   // cell state: one (b,dim) item per thread per layer

    for (int step = 0; step < Sk; step++) {
        const int p = step & 1;
        const float* h0_old = g_h0[p];
        float*       h0_new = g_h0[1 - p];
        const float* h1_old = g_h1[p];
        float*       h1_new = g_h1[1 - p];

        // ================= phase A: layer-0 gates (k = 512, 4 splits x 128) ======
        {
            ull acc[4][2];
#pragma unroll
            for (int i = 0; i < 4; i++) { acc[i][0] = 0ull; acc[i][1] = 0ull; }
            const float* hsrc = h0_old + (size_t)bbase * Hk + split * 128;
            const float* Ws = W0s + split * 128 * 32;
            float* hb = hbufA + split * (KC * HPAD);
            gemm_run(hsrc, Ws, hb, 128 / KC, u, acc);
            combine4(acc, gbuf, sgacc, split, u);
        }
        // activation layer 0: one item per thread
        {
            const int bl = t >> 3, dim = t & 7;
            const int bg = bbase + bl;
            const float4 xa = *(const float4*)(x + ((size_t)bg * Sk + step) * Fk);
            const float4 xb = *(const float4*)(x + ((size_t)bg * Sk + step) * Fk + 4);
            float gate[4];
#pragma unroll
            for (int g = 0; g < 4; g++) {
                const int col = g * 8 + dim;
                const float* wv = Wih0s + col * 8;
                float s = gbuf[bl * 33 + col] + b0s[col];
                s += xa.x * wv[0] + xa.y * wv[1] + xa.z * wv[2] + xa.w * wv[3];
                s += xb.x * wv[4] + xb.y * wv[5] + xb.z * wv[6] + xb.w * wv[7];
                gate[g] = s;
            }
            const float ig = sigf(gate[0]);
            const float fg = sigf(gate[1]);
            const float gg = tanh_f(gate[2]);
            const float og = sigf(gate[3]);
            const float cn = fg * c0 + ig * gg;
            c0 = cn;
            h0_new[(size_t)bg * Hk + dg * 8 + dim] = og * tanh_f(cn);
        }
        grid_sync();  // h0_new visible everywhere

        // ================= phase B: layer-1 gates (k = 1024, 4 splits x 256) =====
        {
            ull acc[4][2];
#pragma unroll
            for (int i = 0; i < 4; i++) { acc[i][0] = 0ull; acc[i][1] = 0ull; }
            const float* hsrc = (split < 2)
                ? (h0_new + (size_t)bbase * Hk + split * 256)          // W_ih1 @ h0
                : (h1_old + (size_t)bbase * Hk + (split - 2) * 256);   // W_hh1 @ h1
            const float* Ws = W1s + split * 256 * 32;
            float* hb = hbufA + split * (KC * HPAD);
            gemm_run(hsrc, Ws, hb, 256 / KC, u, acc);
            combine4(acc, gbuf, sgacc, split, u);
        }
        // activation layer 1
        {
            const int bl = t >> 3, dim = t & 7;
            const int bg = bbase + bl;
            float gate[4];
#pragma unroll
            for (int g = 0; g < 4; g++) {
                gate[g] = gbuf[bl * 33 + g * 8 + dim] + b1s[g * 8 + dim];
            }
            const float ig = sigf(gate[0]);
            const float fg = sigf(gate[1]);
            const float gg = tanh_f(gate[2]);
            const float og = sigf(gate[3]);
            const float cn = fg * c1 + ig * gg;
            c1 = cn;
            h1_new[(size_t)bg * Hk + dg * 8 + dim] = og * tanh_f(cn);
        }
        grid_sync();  // h1_new visible everywhere

        // ============ FC for this step (CTAs 0..15; overlaps next step) ==========
        if (cta < 16) {
            const int o = cta >> 1;
            const int bh2 = cta & 1;
            const int bl = t >> 3, q = t & 7;
            const int bg = bh2 * 64 + bl;
            const float* hrow = h1_new + (size_t)bg * Hk + q * 64;
            const float* wrow = Wfc + (size_t)o * Hk + q * 64;
            float s = 0.f;
#pragma unroll
            for (int j = 0; j < 16; j++) {
                float4 hv = __ldcg((const float4*)(hrow + j * 4));
                float4 wv = __ldg((const float4*)(wrow + j * 4));
                s = fmaf(hv.x, wv.x, s);
                s = fmaf(hv.y, wv.y, s);
                s = fmaf(hv.z, wv.z, s);
                s = fmaf(hv.w, wv.w, s);
            }
            s += __shfl_xor_sync(0xffffffffu, s, 1);
            s += __shfl_xor_sync(0xffffffffu, s, 2);
            s += __shfl_xor_sync(0xffffffffu, s, 4);
            if (q == 0) {
                out[((size_t)bg * Sk + step) * Ok + o] = s + __ldg(bfc + o);
            }
        }
    }
}

extern "C" void kernel_launch(void* const* d_in, const int* in_sizes, int n_in,
                              void* d_out, int out_size) {
    const float* x    = (const float*)d_in[0];
    const float* Wih0 = (const float*)d_in[1];
    const float* Whh0 = (const float*)d_in[2];
    const float* bih0 = (const float*)d_in[3];
    const float* bhh0 = (const float*)d_in[4];
    const float* Wih1 = (const float*)d_in[5];
    const float* Whh1 = (const float*)d_in[6];
    const float* bih1 = (const float*)d_in[7];
    const float* bhh1 = (const float*)d_in[8];
    const float* Wfc  = (const float*)d_in[9];
    const float* bfc  = (const float*)d_in[10];
    float* out = (float*)d_out;

    cudaFuncSetAttribute(lstm2_kernel,
                         cudaFuncAttributeMaxDynamicSharedMemorySize, SMEM_BYTES);
    lstm2_kernel<<<NCTA, NTHR, SMEM_BYTES>>>(
        x, Wih0, Whh0, bih0, bhh0, Wih1, Whh1, bih1, bhh1, Wfc, bfc, out);
}

// round 4
// speedup vs baseline: 1.3664x; 1.0108x over previous
#include <cuda_runtime.h>

#define NCTA 128
#define NTHR 512
#define Bk 128
#define Sk 1024
#define Fk 8
#define Hk 512
#define Ok 8
#define KC 16
#define HPAD 68

typedef unsigned long long ull;

// persistent device state
__device__ float g_h0[2][Bk * Hk];
__device__ float g_h1[2][Bk * Hk];
__device__ unsigned g_count;   // net-zero after each barrier (sub-based reset)
__device__ unsigned g_epoch;   // monotonic across barriers and graph replays

// ---------------- packed f32x2 helpers ----------------
__device__ __forceinline__ ull pack2(float a, float b) {
    ull r; asm("mov.b64 %0, {%1, %2};" : "=l"(r) : "f"(a), "f"(b)); return r;
}
__device__ __forceinline__ void fma2(ull& d, ull a, ull b) {
    asm("fma.rn.f32x2 %0, %1, %2, %0;" : "+l"(d) : "l"(a), "l"(b));
}
__device__ __forceinline__ float2 unp(ull v) {
    float2 r; asm("mov.b64 {%0, %1}, %2;" : "=f"(r.x), "=f"(r.y) : "l"(v)); return r;
}
__device__ __forceinline__ float sigf(float x) {
    return __fdividef(1.0f, 1.0f + __expf(-x));
}
__device__ __forceinline__ float tanh_f(float x) {
    return 2.0f * sigf(2.0f * x) - 1.0f;
}

// ---------------- software grid barrier ----------------
__device__ __forceinline__ void grid_sync() {
    __syncthreads();
    if (threadIdx.x == 0) {
        __threadfence();
        unsigned e = *(volatile unsigned*)&g_epoch;  // read BEFORE arriving
        unsigned old = atomicAdd(&g_count, 1u);
        if (old == NCTA - 1u) {
            atomicSub(&g_count, (unsigned)NCTA);
            __threadfence();
            atomicAdd(&g_epoch, 1u);
        } else {
            while (*(volatile unsigned*)&g_epoch == e) { }
            __threadfence();
        }
    }
    __syncthreads();
}

// ---------------- GEMM over one k-split (single-buffered hbuf) ----------------
// All 512 threads call this; identical nchunk for every split -> syncs align.
// hsrc: global h source for THIS split (already offset to (bbase, k-offset)).
// Ws:   smem weight rows for THIS split ([k][32], k relative).
// hb:   this split's hbuf base ([KC][HPAD]).
__device__ __forceinline__ void gemm_run(
    const float* __restrict__ hsrc,
    const float* __restrict__ Ws,
    float* hb, int nchunk, int u, ull acc[4][2])
{
    const int cb = (u & 7) * 4;
    const int rb = (u >> 3) * 4;
    const int b0i = u >> 2;          // 0..31
    const int b1i = b0i + 32;        // 32..63
    const int kq = (u & 3) * 4;      // 0,4,8,12

    float4 p0 = __ldcg((const float4*)(hsrc + b0i * Hk + kq));
    float4 p1 = __ldcg((const float4*)(hsrc + b1i * Hk + kq));

    for (int ch = 0; ch < nchunk; ch++) {
        // store the prefetched chunk
        hb[(kq + 0) * HPAD + b0i] = p0.x; hb[(kq + 1) * HPAD + b0i] = p0.y;
        hb[(kq + 2) * HPAD + b0i] = p0.z; hb[(kq + 3) * HPAD + b0i] = p0.w;
        hb[(kq + 0) * HPAD + b1i] = p1.x; hb[(kq + 1) * HPAD + b1i] = p1.y;
        hb[(kq + 2) * HPAD + b1i] = p1.z; hb[(kq + 3) * HPAD + b1i] = p1.w;
        __syncthreads();
        if (ch + 1 < nchunk) {  // issue next chunk's global loads early
            p0 = __ldcg((const float4*)(hsrc + b0i * Hk + (ch + 1) * KC + kq));
            p1 = __ldcg((const float4*)(hsrc + b1i * Hk + (ch + 1) * KC + kq));
        }
        const float* W = Ws + ch * KC * 32;
#pragma unroll
        for (int k = 0; k < KC; k++) {
            ull w01 = *(const ull*)(W + k * 32 + cb);
            ull w23 = *(const ull*)(W + k * 32 + cb + 2);
            float4 h4 = *(const float4*)(hb + k * HPAD + rb);
            ull hp;
            hp = pack2(h4.x, h4.x); fma2(acc[0][0], hp, w01); fma2(acc[0][1], hp, w23);
            hp = pack2(h4.y, h4.y); fma2(acc[1][0], hp, w01); fma2(acc[1][1], hp, w23);
            hp = pack2(h4.z, h4.z); fma2(acc[2][0], hp, w01); fma2(acc[2][1], hp, w23);
            hp = pack2(h4.w, h4.w); fma2(acc[3][0], hp, w01); fma2(acc[3][1], hp, w23);
        }
        __syncthreads();  // hbuf reads done before next store
    }
}

// combine 4 k-split partials -> gbuf [64][33]
__device__ __forceinline__ void combine4(
    ull acc[4][2], float* gbuf, float* sgacc, int split, int u)
{
    const int cb = (u & 7) * 4;
    const int rb = (u >> 3) * 4;
    if (split != 0) {
        float4* sg = (float4*)(sgacc + (split - 1) * 2048 + u * 16);
#pragma unroll
        for (int i = 0; i < 4; i++) {
            float2 a = unp(acc[i][0]), b = unp(acc[i][1]);
            sg[i] = make_float4(a.x, a.y, b.x, b.y);
        }
    }
    __syncthreads();
    if (split == 0) {
        const float4* s1 = (const float4*)(sgacc + 0 * 2048 + u * 16);
        const float4* s2 = (const float4*)(sgacc + 1 * 2048 + u * 16);
        const float4* s3 = (const float4*)(sgacc + 2 * 2048 + u * 16);
#pragma unroll
        for (int i = 0; i < 4; i++) {
            float2 a = unp(acc[i][0]), b = unp(acc[i][1]);
            float4 q1 = s1[i], q2 = s2[i], q3 = s3[i];
            gbuf[(rb + i) * 33 + cb + 0] = a.x + q1.x + q2.x + q3.x;
            gbuf[(rb + i) * 33 + cb + 1] = a.y + q1.y + q2.y + q3.y;
            gbuf[(rb + i) * 33 + cb + 2] = b.x + q1.z + q2.z + q3.z;
            gbuf[(rb + i) * 33 + cb + 3] = b.y + q1.w + q2.w + q3.w;
        }
    }
    __syncthreads();
}

// smem layout (floats):
//   W0s 16384 | W1s 32768 | Wih0s 256 | b0s 32 | b1s 32 | scratch 8256
//   scratch: hbuf (4 splits x KC x HPAD = 4352)  OR  sgacc 6144 + gbuf 2112
#define SMEM_FLOATS (16384 + 32768 + 256 + 32 + 32 + 8256)
#define SMEM_BYTES (SMEM_FLOATS * 4)

extern __shared__ float smem[];

__global__ void __launch_bounds__(NTHR, 1) lstm2_kernel(
    const float* __restrict__ x,
    const float* __restrict__ Wih0, const float* __restrict__ Whh0,
    const float* __restrict__ bih0, const float* __restrict__ bhh0,
    const float* __restrict__ Wih1, const float* __restrict__ Whh1,
    const float* __restrict__ bih1, const float* __restrict__ bhh1,
    const float* __restrict__ Wfc, const float* __restrict__ bfc,
    float* __restrict__ out)
{
    float* W0s    = smem;                     // [512][32]
    float* W1s    = W0s + 512 * 32;           // [1024][32]
    float* Wih0s  = W1s + 1024 * 32;          // [32][8]
    float* b0s    = Wih0s + 256;              // [32]
    float* b1s    = b0s + 32;                 // [32]
    float* scratch = b1s + 32;
    float* hbufA  = scratch;                  // [4 splits][KC][HPAD]
    float* sgacc  = scratch;                  // [3][2048] (after hbuf dead)
    float* gbuf   = scratch + 6144;           // [64][33]

    const int t = threadIdx.x;
    const int cta = blockIdx.x;
    const int dg = cta >> 1;        // hidden-dim group: dims dg*8 .. dg*8+7
    const int bh = cta & 1;         // batch half
    const int bbase = bh * 64;
    const int split = t >> 7;       // k-split 0..3
    const int u = t & 127;

    // ---- load weight slices into smem (coalesced along k) ----
    for (int c = 0; c < 32; c++) {
        const int grow = ((c >> 3) * Hk) + dg * 8 + (c & 7);  // gate-major row
        const float* s0 = Whh0 + (size_t)grow * Hk;
        const float* s1 = Wih1 + (size_t)grow * Hk;
        const float* s2 = Whh1 + (size_t)grow * Hk;
        for (int k = t; k < Hk; k += NTHR) {
            W0s[k * 32 + c] = s0[k];
            W1s[k * 32 + c] = s1[k];
            W1s[(Hk + k) * 32 + c] = s2[k];
        }
    }
    if (t < 256) {
        const int c = t >> 3, k = t & 7;
        const int grow = ((c >> 3) * Hk) + dg * 8 + (c & 7);
        Wih0s[c * 8 + k] = Wih0[grow * Fk + k];
    }
    if (t < 32) {
        const int grow = ((t >> 3) * Hk) + dg * 8 + (t & 7);
        b0s[t] = bih0[grow] + bhh0[grow];
        b1s[t] = bih1[grow] + bhh1[grow];
    }
    // zero both parities of h state
    for (int i = cta * NTHR + t; i < 2 * Bk * Hk; i += NCTA * NTHR) {
        ((float*)g_h0)[i] = 0.0f;
        ((float*)g_h1)[i] = 0.0f;
    }
    grid_sync();

    float c0 = 0.f, c1 = 0.f;   // cell state: one (b,dim) item per thread per layer

    for (int step = 0; step < Sk; step++) {
        const int p = step & 1;
        const float* h0_old = g_h0[p];
        float*       h0_new = g_h0[1 - p];
        const float* h1_old = g_h1[p];
        float*       h1_new = g_h1[1 - p];

        // ================= phase A: layer-0 gates (k = 512, 4 splits x 128) ======
        {
            ull acc[4][2];
#pragma unroll
            for (int i = 0; i < 4; i++) { acc[i][0] = 0ull; acc[i][1] = 0ull; }
            const float* hsrc = h0_old + (size_t)bbase * Hk + split * 128;
            const float* Ws = W0s + split * 128 * 32;
            float* hb = hbufA + split * (KC * HPAD);
            gemm_run(hsrc, Ws, hb, 128 / KC, u, acc);
            combine4(acc, gbuf, sgacc, split, u);
        }
        // activation layer 0: one item per thread
        {
            const int bl = t >> 3, dim = t & 7;
            const int bg = bbase + bl;
            const float4 xa = *(const float4*)(x + ((size_t)bg * Sk + step) * Fk);
            const float4 xb = *(const float4*)(x + ((size_t)bg * Sk + step) * Fk + 4);
            float gate[4];
#pragma unroll
            for (int g = 0; g < 4; g++) {
                const int col = g * 8 + dim;
                const float* wv = Wih0s + col * 8;
                float s = gbuf[bl * 33 + col] + b0s[col];
                s += xa.x * wv[0] + xa.y * wv[1] + xa.z * wv[2] + xa.w * wv[3];
                s += xb.x * wv[4] + xb.y * wv[5] + xb.z * wv[6] + xb.w * wv[7];
                gate[g] = s;
            }
            const float ig = sigf(gate[0]);
            const float fg = sigf(gate[1]);
            const float gg = tanh_f(gate[2]);
            const float og = sigf(gate[3]);
            const float cn = fg * c0 + ig * gg;
            c0 = cn;
            h0_new[(size_t)bg * Hk + dg * 8 + dim] = og * tanh_f(cn);
        }
        grid_sync();  // h0_new visible everywhere

        // ================= phase B: layer-1 gates (k = 1024, 4 splits x 256) =====
        {
            ull acc[4][2];
#pragma unroll
            for (int i = 0; i < 4; i++) { acc[i][0] = 0ull; acc[i][1] = 0ull; }
            const float* hsrc = (split < 2)
                ? (h0_new + (size_t)bbase * Hk + split * 256)          // W_ih1 @ h0
                : (h1_old + (size_t)bbase * Hk + (split - 2) * 256);   // W_hh1 @ h1
            const float* Ws = W1s + split * 256 * 32;
            float* hb = hbufA + split * (KC * HPAD);
            gemm_run(hsrc, Ws, hb, 256 / KC, u, acc);
            combine4(acc, gbuf, sgacc, split, u);
        }
        // activation layer 1
        {
            const int bl = t >> 3, dim = t & 7;
            const int bg = bbase + bl;
            float gate[4];
#pragma unroll
            for (int g = 0; g < 4; g++) {
                gate[g] = gbuf[bl * 33 + g * 8 + dim] + b1s[g * 8 + dim];
            }
            const float ig = sigf(gate[0]);
            const float fg = sigf(gate[1]);
            const float gg = tanh_f(gate[2]);
            const float og = sigf(gate[3]);
            const float cn = fg * c1 + ig * gg;
            c1 = cn;
            h1_new[(size_t)bg * Hk + dg * 8 + dim] = og * tanh_f(cn);
        }
        grid_sync();  // h1_new visible everywhere

        // ============ FC for this step (CTAs 0..15; overlaps next step) ==========
        if (cta < 16) {
            const int o = cta >> 1;
            const int bh2 = cta & 1;
            const int bl = t >> 3, q = t & 7;
            const int bg = bh2 * 64 + bl;
            const float* hrow = h1_new + (size_t)bg * Hk + q * 64;
            const float* wrow = Wfc + (size_t)o * Hk + q * 64;
            float s = 0.f;
#pragma unroll
            for (int j = 0; j < 16; j++) {
                float4 hv = __ldcg((const float4*)(hrow + j * 4));
                float4 wv = __ldg((const float4*)(wrow + j * 4));
                s = fmaf(hv.x, wv.x, s);
                s = fmaf(hv.y, wv.y, s);
                s = fmaf(hv.z, wv.z, s);
                s = fmaf(hv.w, wv.w, s);
            }
            s += __shfl_xor_sync(0xffffffffu, s, 1);
            s += __shfl_xor_sync(0xffffffffu, s, 2);
            s += __shfl_xor_sync(0xffffffffu, s, 4);
            if (q == 0) {
                out[((size_t)bg * Sk + step) * Ok + o] = s + __ldg(bfc + o);
            }
        }
    }
}

extern "C" void kernel_launch(void* const* d_in, const int* in_sizes, int n_in,
                              void* d_out, int out_size) {
    const float* x    = (const float*)d_in[0];
    const float* Wih0 = (const float*)d_in[1];
    const float* Whh0 = (const float*)d_in[2];
    const float* bih0 = (const float*)d_in[3];
    const float* bhh0 = (const float*)d_in[4];
    const float* Wih1 = (const float*)d_in[5];
    const float* Whh1 = (const float*)d_in[6];
    const float* bih1 = (const float*)d_in[7];
    const float* bhh1 = (const float*)d_in[8];
    const float* Wfc  = (const float*)d_in[9];
    const float* bfc  = (const float*)d_in[10];
    float* out = (float*)d_out;

    cudaFuncSetAttribute(lstm2_kernel,
                         cudaFuncAttributeMaxDynamicSharedMemorySize, SMEM_BYTES);
    lstm2_kernel<<<NCTA, NTHR, SMEM_BYTES>>>(
        x, Wih0, Whh0, bih0, bhh0, Wih1, Whh1, bih1, bhh1, Wfc, bfc, out);
}

// round 7
// speedup vs baseline: 1.5068x; 1.1027x over previous
#include <cuda_runtime.h>
#include <cuda_bf16.h>
#include <cstdint>

#define NCTA 128
#define NTHR 256
#define Bk 128
#define Sk 1024
#define Fk 8
#define Hk 512
#define Ok 8

// ---------------- persistent device state ----------------
// Fragment-packed weights: [plane][midx=mt*4+gate][kb][lane] -> uint4 (8 bf16)
__device__ uint4 gWf0[2][128][32][32];   // layer0: k=512  (4 MB)
__device__ uint4 gWf1[2][128][64][32];   // layer1: k=1024 (8 MB)
// h planes: [parity][plane hi/lo][n*512+k]
__device__ __nv_bfloat16 gh0[2][2][Bk * Hk];
__device__ __nv_bfloat16 gh1[2][2][Bk * Hk];
__device__ float gh1f[2][Bk * Hk];       // fp32 h1 for FC
__device__ unsigned g_count, g_epoch;

// ---------------- helpers ----------------
__device__ __forceinline__ float sigf(float x) { return __fdividef(1.0f, 1.0f + __expf(-x)); }
__device__ __forceinline__ float tanh_f(float x) { return 2.0f * sigf(2.0f * x) - 1.0f; }

__device__ __forceinline__ uint32_t f2bf2u(float a, float b) {
    __nv_bfloat162 v = __floats2bfloat162_rn(a, b);
    return *reinterpret_cast<uint32_t*>(&v);
}

__device__ __forceinline__ void mma16816(float* c, uint4 a, uint32_t b0, uint32_t b1) {
    asm volatile(
        "mma.sync.aligned.m16n8k16.row.col.f32.bf16.bf16.f32 "
        "{%0,%1,%2,%3}, {%4,%5,%6,%7}, {%8,%9}, {%0,%1,%2,%3};"
        : "+f"(c[0]), "+f"(c[1]), "+f"(c[2]), "+f"(c[3])
        : "r"(a.x), "r"(a.y), "r"(a.z), "r"(a.w), "r"(b0), "r"(b1));
}

__device__ __forceinline__ uint32_t ldcg_u32(const __nv_bfloat16* p) {
    return __ldcg(reinterpret_cast<const unsigned int*>(p));
}

// ---------------- software grid barrier ----------------
__device__ __forceinline__ void grid_sync() {
    __syncthreads();
    if (threadIdx.x == 0) {
        __threadfence();
        unsigned e = *(volatile unsigned*)&g_epoch;
        unsigned old = atomicAdd(&g_count, 1u);
        if (old == NCTA - 1u) {
            atomicSub(&g_count, (unsigned)NCTA);
            __threadfence();
            atomicAdd(&g_epoch, 1u);
        } else {
            while (*(volatile unsigned*)&g_epoch == e) { }
            __threadfence();
        }
    }
    __syncthreads();
}

__global__ void __launch_bounds__(NTHR, 1) lstm2_mma_kernel(
    const float* __restrict__ x,
    const float* __restrict__ Wih0, const float* __restrict__ Whh0,
    const float* __restrict__ bih0, const float* __restrict__ bhh0,
    const float* __restrict__ Wih1, const float* __restrict__ Whh1,
    const float* __restrict__ bih1, const float* __restrict__ bhh1,
    const float* __restrict__ Wfc, const float* __restrict__ bfc,
    float* __restrict__ out)
{
    __shared__ float sg[4 * 16 * 33];   // [gate][dl][n] gate exchange
    __shared__ float xs[32 * 8];        // x slab for this step
    __shared__ float wih0s[64 * 9];     // [g*16+dl][f], padded
    __shared__ float b0s[64], b1s[64];

    const int t = threadIdx.x;
    const int cta = blockIdx.x;
    const int mt = cta >> 2;        // dim block: dims mt*16 .. mt*16+15
    const int nt = cta & 3;         // batch slab: nt*32 .. nt*32+31
    const int nb_base = nt * 32;
    const int wid = t >> 5, lane = t & 31;
    const int mi = wid >> 1;        // gate 0..3
    const int ni = wid & 1;         // n half 0..1
    const int g8 = lane >> 2;       // fragment group row/col
    const int tq = lane & 3;
    const int midx = mt * 4 + mi;

    // ============ pre-pass: fragment-pack weights, zero h ============
    {
        const int gt = cta * NTHR + t;
        const int NT = NCTA * NTHR;
        uint4* w0p = &gWf0[0][0][0][0];
        for (int i = gt; i < 2 * 128 * 32 * 32; i += NT) {
            const int ln = i & 31, kb = (i >> 5) & 31, mx = (i >> 10) & 127, pl = i >> 17;
            const int mtt = mx >> 2, mii = mx & 3;
            const int gg = ln >> 2, tt = ln & 3;
            uint32_t r[4];
#pragma unroll
            for (int rr = 0; rr < 4; rr++) {
                const int row = mii * 512 + mtt * 16 + gg + (rr & 1) * 8;
                const int k = kb * 16 + tt * 2 + (rr >> 1) * 8;
                float v0 = __ldg(Whh0 + (size_t)row * 512 + k);
                float v1 = __ldg(Whh0 + (size_t)row * 512 + k + 1);
                if (pl) {
                    v0 -= __bfloat162float(__float2bfloat16(v0));
                    v1 -= __bfloat162float(__float2bfloat16(v1));
                }
                r[rr] = f2bf2u(v0, v1);
            }
            w0p[i] = make_uint4(r[0], r[1], r[2], r[3]);
        }
        uint4* w1p = &gWf1[0][0][0][0];
        for (int i = gt; i < 2 * 128 * 64 * 32; i += NT) {
            const int ln = i & 31, kb = (i >> 5) & 63, mx = (i >> 11) & 127, pl = i >> 18;
            const int mtt = mx >> 2, mii = mx & 3;
            const int gg = ln >> 2, tt = ln & 3;
            const float* src = (kb < 32) ? Wih1 : Whh1;
            const int kb2 = (kb < 32) ? kb : (kb - 32);
            uint32_t r[4];
#pragma unroll
            for (int rr = 0; rr < 4; rr++) {
                const int row = mii * 512 + mtt * 16 + gg + (rr & 1) * 8;
                const int k = kb2 * 16 + tt * 2 + (rr >> 1) * 8;
                float v0 = __ldg(src + (size_t)row * 512 + k);
                float v1 = __ldg(src + (size_t)row * 512 + k + 1);
                if (pl) {
                    v0 -= __bfloat162float(__float2bfloat16(v0));
                    v1 -= __bfloat162float(__float2bfloat16(v1));
                }
                r[rr] = f2bf2u(v0, v1);
            }
            w1p[i] = make_uint4(r[0], r[1], r[2], r[3]);
        }
        const __nv_bfloat16 z = __float2bfloat16(0.0f);
        for (int i = gt; i < 2 * 2 * Bk * Hk; i += NT) {
            (&gh0[0][0][0])[i] = z;
            (&gh1[0][0][0])[i] = z;
        }
        for (int i = gt; i < 2 * Bk * Hk; i += NT) (&gh1f[0][0])[i] = 0.0f;
    }
    // per-CTA smem constants
    for (int j = t; j < 512; j += NTHR) {
        const int rl = j >> 3, f = j & 7;
        const int grow = (rl >> 4) * 512 + mt * 16 + (rl & 15);
        wih0s[rl * 9 + f] = __ldg(Wih0 + (size_t)grow * 8 + f);
    }
    if (t < 64) {
        const int grow = (t >> 4) * 512 + mt * 16 + (t & 15);
        b0s[t] = __ldg(bih0 + grow) + __ldg(bhh0 + grow);
        b1s[t] = __ldg(bih1 + grow) + __ldg(bhh1 + grow);
    }
    grid_sync();

    // B-fragment n offsets (elements) for the two n8 blocks this warp covers
    const int n_g0 = nb_base + ni * 16 + 0 + g8;
    const int n_g1 = nb_base + ni * 16 + 8 + g8;
    const size_t boff0 = (size_t)n_g0 * Hk;
    const size_t boff1 = (size_t)n_g1 * Hk;

    float c0r[2] = {0.f, 0.f}, c1r[2] = {0.f, 0.f};

    for (int step = 0; step < Sk; step++) {
        const int p = step & 1;

        // ---------------- phase A: layer-0 gates (k=512) ----------------
        {
            const int n = t >> 3, f = t & 7;  // stage x
            xs[n * 8 + f] = __ldg(x + ((size_t)(nb_base + n) * Sk + step) * Fk + f);
        }
        {
            float acc0[4] = {0, 0, 0, 0}, acc1[4] = {0, 0, 0, 0};
            const __nv_bfloat16* sH = gh0[p][0];
            const __nv_bfloat16* sL = gh0[p][1];
            uint4 aH = __ldg(&gWf0[0][midx][0][lane]);
            uint4 aL = __ldg(&gWf0[1][midx][0][lane]);
            const int kk0 = tq * 2;
            uint32_t bH00 = ldcg_u32(sH + boff0 + kk0), bH01 = ldcg_u32(sH + boff0 + kk0 + 8);
            uint32_t bH10 = ldcg_u32(sH + boff1 + kk0), bH11 = ldcg_u32(sH + boff1 + kk0 + 8);
            uint32_t bL00 = ldcg_u32(sL + boff0 + kk0), bL01 = ldcg_u32(sL + boff0 + kk0 + 8);
            uint32_t bL10 = ldcg_u32(sL + boff1 + kk0), bL11 = ldcg_u32(sL + boff1 + kk0 + 8);
#pragma unroll 4
            for (int c = 0; c < 32; c++) {
                uint4 aHn, aLn;
                uint32_t nH00, nH01, nH10, nH11, nL00, nL01, nL10, nL11;
                if (c + 1 < 32) {
                    aHn = __ldg(&gWf0[0][midx][c + 1][lane]);
                    aLn = __ldg(&gWf0[1][midx][c + 1][lane]);
                    const int kk = (c + 1) * 16 + tq * 2;
                    nH00 = ldcg_u32(sH + boff0 + kk); nH01 = ldcg_u32(sH + boff0 + kk + 8);
                    nH10 = ldcg_u32(sH + boff1 + kk); nH11 = ldcg_u32(sH + boff1 + kk + 8);
                    nL00 = ldcg_u32(sL + boff0 + kk); nL01 = ldcg_u32(sL + boff0 + kk + 8);
                    nL10 = ldcg_u32(sL + boff1 + kk); nL11 = ldcg_u32(sL + boff1 + kk + 8);
                }
                mma16816(acc0, aH, bH00, bH01);
                mma16816(acc1, aH, bH10, bH11);
                mma16816(acc0, aH, bL00, bL01);
                mma16816(acc1, aH, bL10, bL11);
                mma16816(acc0, aL, bH00, bH01);
                mma16816(acc1, aL, bH10, bH11);
                if (c + 1 < 32) {
                    aH = aHn; aL = aLn;
                    bH00 = nH00; bH01 = nH01; bH10 = nH10; bH11 = nH11;
                    bL00 = nL00; bL01 = nL01; bL10 = nL10; bL11 = nL11;
                }
            }
            // write accums to gate-exchange smem: sg[gate][dl][n]
            float* sgm = sg + mi * (16 * 33);
            const int ncol = ni * 16 + tq * 2;
            sgm[g8 * 33 + ncol + 0] = acc0[0];
            sgm[g8 * 33 + ncol + 1] = acc0[1];
            sgm[(g8 + 8) * 33 + ncol + 0] = acc0[2];
            sgm[(g8 + 8) * 33 + ncol + 1] = acc0[3];
            sgm[g8 * 33 + ncol + 8 + 0] = acc1[0];
            sgm[g8 * 33 + ncol + 8 + 1] = acc1[1];
            sgm[(g8 + 8) * 33 + ncol + 8 + 0] = acc1[2];
            sgm[(g8 + 8) * 33 + ncol + 8 + 1] = acc1[3];
        }
        __syncthreads();
        // activation layer 0: 2 items/thread
#pragma unroll
        for (int i = 0; i < 2; i++) {
            const int idx = i * NTHR + t;
            const int n = idx >> 4, dl = idx & 15;
            float gate[4];
#pragma unroll
            for (int g = 0; g < 4; g++) {
                float s = sg[g * (16 * 33) + dl * 33 + n] + b0s[g * 16 + dl];
                const float* wv = wih0s + (g * 16 + dl) * 9;
                const float* xv = xs + n * 8;
#pragma unroll
                for (int f = 0; f < 8; f++) s = fmaf(xv[f], wv[f], s);
                gate[g] = s;
            }
            const float cn = sigf(gate[1]) * c0r[i] + sigf(gate[0]) * tanh_f(gate[2]);
            c0r[i] = cn;
            const float h = sigf(gate[3]) * tanh_f(cn);
            const size_t off = (size_t)(nb_base + n) * Hk + mt * 16 + dl;
            const __nv_bfloat16 hi = __float2bfloat16(h);
            gh0[1 - p][0][off] = hi;
            gh0[1 - p][1][off] = __float2bfloat16(h - __bfloat162float(hi));
        }
        grid_sync();  // h0_new visible

        // ---------------- phase B: layer-1 gates (k=1024) ----------------
        {
            float acc0[4] = {0, 0, 0, 0}, acc1[4] = {0, 0, 0, 0};
            const __nv_bfloat16* h0H = gh0[1 - p][0];
            const __nv_bfloat16* h0L = gh0[1 - p][1];
            const __nv_bfloat16* h1H = gh1[p][0];
            const __nv_bfloat16* h1L = gh1[p][1];
            uint4 aH = __ldg(&gWf1[0][midx][0][lane]);
            uint4 aL = __ldg(&gWf1[1][midx][0][lane]);
            const int kk0 = tq * 2;
            uint32_t bH00 = ldcg_u32(h0H + boff0 + kk0), bH01 = ldcg_u32(h0H + boff0 + kk0 + 8);
            uint32_t bH10 = ldcg_u32(h0H + boff1 + kk0), bH11 = ldcg_u32(h0H + boff1 + kk0 + 8);
            uint32_t bL00 = ldcg_u32(h0L + boff0 + kk0), bL01 = ldcg_u32(h0L + boff0 + kk0 + 8);
            uint32_t bL10 = ldcg_u32(h0L + boff1 + kk0), bL11 = ldcg_u32(h0L + boff1 + kk0 + 8);
#pragma unroll 4
            for (int c = 0; c < 64; c++) {
                uint4 aHn, aLn;
                uint32_t nH00, nH01, nH10, nH11, nL00, nL01, nL10, nL11;
                if (c + 1 < 64) {
                    aHn = __ldg(&gWf1[0][midx][c + 1][lane]);
                    aLn = __ldg(&gWf1[1][midx][c + 1][lane]);
                    const int cc = c + 1;
                    const __nv_bfloat16* nsH = (cc < 32) ? h0H : h1H;
                    const __nv_bfloat16* nsL = (cc < 32) ? h0L : h1L;
                    const int kk = ((cc < 32) ? cc : (cc - 32)) * 16 + tq * 2;
                    nH00 = ldcg_u32(nsH + boff0 + kk); nH01 = ldcg_u32(nsH + boff0 + kk + 8);
                    nH10 = ldcg_u32(nsH + boff1 + kk); nH11 = ldcg_u32(nsH + boff1 + kk + 8);
                    nL00 = ldcg_u32(nsL + boff0 + kk); nL01 = ldcg_u32(nsL + boff0 + kk + 8);
                    nL10 = ldcg_u32(nsL + boff1 + kk); nL11 = ldcg_u32(nsL + boff1 + kk + 8);
                }
                mma16816(acc0, aH, bH00, bH01);
                mma16816(acc1, aH, bH10, bH11);
                mma16816(acc0, aH, bL00, bL01);
                mma16816(acc1, aH, bL10, bL11);
                mma16816(acc0, aL, bH00, bH01);
                mma16816(acc1, aL, bH10, bH11);
                if (c + 1 < 64) {
                    aH = aHn; aL = aLn;
                    bH00 = nH00; bH01 = nH01; bH10 = nH10; bH11 = nH11;
                    bL00 = nL00; bL01 = nL01; bL10 = nL10; bL11 = nL11;
                }
            }
            float* sgm = sg + mi * (16 * 33);
            const int ncol = ni * 16 + tq * 2;
            sgm[g8 * 33 + ncol + 0] = acc0[0];
            sgm[g8 * 33 + ncol + 1] = acc0[1];
            sgm[(g8 + 8) * 33 + ncol + 0] = acc0[2];
            sgm[(g8 + 8) * 33 + ncol + 1] = acc0[3];
            sgm[g8 * 33 + ncol + 8 + 0] = acc1[0];
            sgm[g8 * 33 + ncol + 8 + 1] = acc1[1];
            sgm[(g8 + 8) * 33 + ncol + 8 + 0] = acc1[2];
            sgm[(g8 + 8) * 33 + ncol + 8 + 1] = acc1[3];
        }
        __syncthreads();
        // activation layer 1
#pragma unroll
        for (int i = 0; i < 2; i++) {
            const int idx = i * NTHR + t;
            const int n = idx >> 4, dl = idx & 15;
            float gate[4];
#pragma unroll
            for (int g = 0; g < 4; g++)
                gate[g] = sg[g * (16 * 33) + dl * 33 + n] + b1s[g * 16 + dl];
            const float cn = sigf(gate[1]) * c1r[i] + sigf(gate[0]) * tanh_f(gate[2]);
            c1r[i] = cn;
            const float h = sigf(gate[3]) * tanh_f(cn);
            const size_t off = (size_t)(nb_base + n) * Hk + mt * 16 + dl;
            const __nv_bfloat16 hi = __float2bfloat16(h);
            gh1[1 - p][0][off] = hi;
            gh1[1 - p][1][off] = __float2bfloat16(h - __bfloat162float(hi));
            gh1f[1 - p][off] = h;
        }
        grid_sync();  // h1_new visible

        // ---------------- FC for this step (batch row = cta) ----------------
        {
            const int o = t >> 5;
            const int l = t & 31;
            const float* hrow = gh1f[1 - p] + (size_t)cta * Hk;
            const float* wrow = Wfc + (size_t)o * Hk;
            float s = 0.f;
#pragma unroll
            for (int j = 0; j < 16; j++) {
                const int k = l + j * 32;
                s = fmaf(__ldcg(hrow + k), __ldg(wrow + k), s);
            }
#pragma unroll
            for (int off = 16; off > 0; off >>= 1)
                s += __shfl_xor_sync(0xffffffffu, s, off);
            if (l == 0)
                out[((size_t)cta * Sk + step) * Ok + o] = s + __ldg(bfc + o);
        }
    }
}

extern "C" void kernel_launch(void* const* d_in, const int* in_sizes, int n_in,
                              void* d_out, int out_size) {
    const float* x    = (const float*)d_in[0];
    const float* Wih0 = (const float*)d_in[1];
    const float* Whh0 = (const float*)d_in[2];
    const float* bih0 = (const float*)d_in[3];
    const float* bhh0 = (const float*)d_in[4];
    const float* Wih1 = (const float*)d_in[5];
    const float* Whh1 = (const float*)d_in[6];
    const float* bih1 = (const float*)d_in[7];
    const float* bhh1 = (const float*)d_in[8];
    const float* Wfc  = (const float*)d_in[9];
    const float* bfc  = (const float*)d_in[10];
    float* out = (float*)d_out;

    lstm2_mma_kernel<<<NCTA, NTHR>>>(
        x, Wih0, Whh0, bih0, bhh0, Wih1, Whh1, bih1, bhh1, Wfc, bfc, out);
}

// round 9
// speedup vs baseline: 1.6714x; 1.1093x over previous
#include <cuda_runtime.h>
#include <cuda_bf16.h>
#include <cstdint>

#define NCTA 128
#define NTHR 512
#define Bk 128
#define Sk 1024
#define Fk 8
#define Hk 512
#define Ok 8

// ---------------- persistent device state ----------------
// Fragment-packed weights: [plane][midx=mt*4+gate][kb][lane] -> uint4 (8 bf16)
__device__ uint4 gWf0[2][128][32][32];   // layer0: k=512  (4 MB)
__device__ uint4 gWf1[2][128][64][32];   // layer1: k=1024 (8 MB)
// h planes: [parity][plane hi/lo][n*512+k]
__device__ __nv_bfloat16 gh0[2][2][Bk * Hk];
__device__ __nv_bfloat16 gh1[2][2][Bk * Hk];
__device__ float gh1f[2][Bk * Hk];       // fp32 h1 for FC
__device__ unsigned g_count, g_epoch;

// ---------------- helpers ----------------
__device__ __forceinline__ float sigf(float x) { return __fdividef(1.0f, 1.0f + __expf(-x)); }
__device__ __forceinline__ float tanh_f(float x) { return 2.0f * sigf(2.0f * x) - 1.0f; }

__device__ __forceinline__ uint32_t f2bf2u(float a, float b) {
    __nv_bfloat162 v = __floats2bfloat162_rn(a, b);
    return *reinterpret_cast<uint32_t*>(&v);
}

__device__ __forceinline__ void mma16816(float* c, uint4 a, uint32_t b0, uint32_t b1) {
    asm volatile(
        "mma.sync.aligned.m16n8k16.row.col.f32.bf16.bf16.f32 "
        "{%0,%1,%2,%3}, {%4,%5,%6,%7}, {%8,%9}, {%0,%1,%2,%3};"
        : "+f"(c[0]), "+f"(c[1]), "+f"(c[2]), "+f"(c[3])
        : "r"(a.x), "r"(a.y), "r"(a.z), "r"(a.w), "r"(b0), "r"(b1));
}

__device__ __forceinline__ uint32_t ldcg_u32(const __nv_bfloat16* p) {
    return __ldcg(reinterpret_cast<const unsigned int*>(p));
}

// ---------------- software grid barrier ----------------
__device__ __forceinline__ void grid_sync() {
    __syncthreads();
    if (threadIdx.x == 0) {
        __threadfence();
        unsigned e = *(volatile unsigned*)&g_epoch;
        unsigned old = atomicAdd(&g_count, 1u);
        if (old == NCTA - 1u) {
            atomicSub(&g_count, (unsigned)NCTA);
            __threadfence();
            atomicAdd(&g_epoch, 1u);
        } else {
            while (*(volatile unsigned*)&g_epoch == e) { }
            __threadfence();
        }
    }
    __syncthreads();
}

// ---------------- one k-span of 3-product bf16-split MMA ----------------
// sH/sL: h planes, pre-offset so local k starts at 0 for this warp's span.
// wH/wL: fragment-packed weight pointers for this warp's (midx, kb-base, lane);
//        stride 32 uint4 per k-slab.
__device__ __forceinline__ void gemm_span(
    const __nv_bfloat16* __restrict__ sH, const __nv_bfloat16* __restrict__ sL,
    const uint4* __restrict__ wH, const uint4* __restrict__ wL, int nslab,
    size_t boff0, size_t boff1, int tq, float* acc0, float* acc1)
{
    uint4 aH = __ldg(wH);
    uint4 aL = __ldg(wL);
    const int kk0 = tq * 2;
    uint32_t bH00 = ldcg_u32(sH + boff0 + kk0), bH01 = ldcg_u32(sH + boff0 + kk0 + 8);
    uint32_t bH10 = ldcg_u32(sH + boff1 + kk0), bH11 = ldcg_u32(sH + boff1 + kk0 + 8);
    uint32_t bL00 = ldcg_u32(sL + boff0 + kk0), bL01 = ldcg_u32(sL + boff0 + kk0 + 8);
    uint32_t bL10 = ldcg_u32(sL + boff1 + kk0), bL11 = ldcg_u32(sL + boff1 + kk0 + 8);
#pragma unroll 4
    for (int c = 0; c < nslab; c++) {
        uint4 aHn, aLn;
        uint32_t nH00, nH01, nH10, nH11, nL00, nL01, nL10, nL11;
        if (c + 1 < nslab) {
            aHn = __ldg(wH + (c + 1) * 32);
            aLn = __ldg(wL + (c + 1) * 32);
            const int kk = (c + 1) * 16 + tq * 2;
            nH00 = ldcg_u32(sH + boff0 + kk); nH01 = ldcg_u32(sH + boff0 + kk + 8);
            nH10 = ldcg_u32(sH + boff1 + kk); nH11 = ldcg_u32(sH + boff1 + kk + 8);
            nL00 = ldcg_u32(sL + boff0 + kk); nL01 = ldcg_u32(sL + boff0 + kk + 8);
            nL10 = ldcg_u32(sL + boff1 + kk); nL11 = ldcg_u32(sL + boff1 + kk + 8);
        }
        mma16816(acc0, aH, bH00, bH01);
        mma16816(acc1, aH, bH10, bH11);
        mma16816(acc0, aH, bL00, bL01);
        mma16816(acc1, aH, bL10, bL11);
        mma16816(acc0, aL, bH00, bH01);
        mma16816(acc1, aL, bH10, bH11);
        if (c + 1 < nslab) {
            aH = aHn; aL = aLn;
            bH00 = nH00; bH01 = nH01; bH10 = nH10; bH11 = nH11;
            bL00 = nL00; bL01 = nL01; bL10 = nL10; bL11 = nL11;
        }
    }
}

__global__ void __launch_bounds__(NTHR, 1) lstm2_mma_kernel(
    const float* __restrict__ x,
    const float* __restrict__ Wih0, const float* __restrict__ Whh0,
    const float* __restrict__ bih0, const float* __restrict__ bhh0,
    const float* __restrict__ Wih1, const float* __restrict__ Whh1,
    const float* __restrict__ bih1, const float* __restrict__ bhh1,
    const float* __restrict__ Wfc, const float* __restrict__ bfc,
    float* __restrict__ out)
{
    __shared__ float sg[2 * 4 * 16 * 33];  // [kh][gate][dl][n] partial sums
    __shared__ float xs[32 * 8];           // x slab for this step
    __shared__ float wih0s[64 * 9];        // [g*16+dl][f], padded
    __shared__ float b0s[64], b1s[64];

    const int t = threadIdx.x;
    const int cta = blockIdx.x;
    const int mt = cta >> 2;        // dim block: dims mt*16 .. mt*16+15
    const int nt = cta & 3;         // batch slab: nt*32 .. nt*32+31
    const int nb_base = nt * 32;
    const int wid = t >> 5, lane = t & 31;
    const int kh = wid >> 3;        // k-half 0..1
    const int mi = (wid >> 1) & 3;  // gate 0..3
    const int ni = wid & 1;         // n half 0..1
    const int g8 = lane >> 2;       // fragment group row/col
    const int tq = lane & 3;
    const int midx = mt * 4 + mi;

    // ============ pre-pass: fragment-pack weights, zero h ============
    {
        const int gt = cta * NTHR + t;
        const int NT = NCTA * NTHR;
        uint4* w0p = &gWf0[0][0][0][0];
        for (int i = gt; i < 2 * 128 * 32 * 32; i += NT) {
            const int ln = i & 31, kb = (i >> 5) & 31, mx = (i >> 10) & 127, pl = i >> 17;
            const int mtt = mx >> 2, mii = mx & 3;
            const int gg = ln >> 2, tt = ln & 3;
            uint32_t r[4];
#pragma unroll
            for (int rr = 0; rr < 4; rr++) {
                const int row = mii * 512 + mtt * 16 + gg + (rr & 1) * 8;
                const int k = kb * 16 + tt * 2 + (rr >> 1) * 8;
                float v0 = __ldg(Whh0 + (size_t)row * 512 + k);
                float v1 = __ldg(Whh0 + (size_t)row * 512 + k + 1);
                if (pl) {
                    v0 -= __bfloat162float(__float2bfloat16(v0));
                    v1 -= __bfloat162float(__float2bfloat16(v1));
                }
                r[rr] = f2bf2u(v0, v1);
            }
            w0p[i] = make_uint4(r[0], r[1], r[2], r[3]);
        }
        uint4* w1p = &gWf1[0][0][0][0];
        for (int i = gt; i < 2 * 128 * 64 * 32; i += NT) {
            const int ln = i & 31, kb = (i >> 5) & 63, mx = (i >> 11) & 127, pl = i >> 18;
            const int mtt = mx >> 2, mii = mx & 3;
            const int gg = ln >> 2, tt = ln & 3;
            const float* src = (kb < 32) ? Wih1 : Whh1;
            const int kb2 = (kb < 32) ? kb : (kb - 32);
            uint32_t r[4];
#pragma unroll
            for (int rr = 0; rr < 4; rr++) {
                const int row = mii * 512 + mtt * 16 + gg + (rr & 1) * 8;
                const int k = kb2 * 16 + tt * 2 + (rr >> 1) * 8;
                float v0 = __ldg(src + (size_t)row * 512 + k);
                float v1 = __ldg(src + (size_t)row * 512 + k + 1);
                if (pl) {
                    v0 -= __bfloat162float(__float2bfloat16(v0));
                    v1 -= __bfloat162float(__float2bfloat16(v1));
                }
                r[rr] = f2bf2u(v0, v1);
            }
            w1p[i] = make_uint4(r[0], r[1], r[2], r[3]);
        }
        const __nv_bfloat16 z = __float2bfloat16(0.0f);
        for (int i = gt; i < 2 * 2 * Bk * Hk; i += NT) {
            (&gh0[0][0][0])[i] = z;
            (&gh1[0][0][0])[i] = z;
        }
        for (int i = gt; i < 2 * Bk * Hk; i += NT) (&gh1f[0][0])[i] = 0.0f;
    }
    // per-CTA smem constants
    for (int j = t; j < 512; j += NTHR) {
        const int rl = j >> 3, f = j & 7;
        const int grow = (rl >> 4) * 512 + mt * 16 + (rl & 15);
        wih0s[rl * 9 + f] = __ldg(Wih0 + (size_t)grow * 8 + f);
    }
    if (t < 64) {
        const int grow = (t >> 4) * 512 + mt * 16 + (t & 15);
        b0s[t] = __ldg(bih0 + grow) + __ldg(bhh0 + grow);
        b1s[t] = __ldg(bih1 + grow) + __ldg(bhh1 + grow);
    }
    grid_sync();

    // B-fragment n offsets (elements) for this warp's two n8 blocks
    const int n_g0 = nb_base + ni * 16 + 0 + g8;
    const int n_g1 = nb_base + ni * 16 + 8 + g8;
    const size_t boff0 = (size_t)n_g0 * Hk;
    const size_t boff1 = (size_t)n_g1 * Hk;

    // activation item for this thread
    const int an = t >> 4, adl = t & 15;
    float c0r = 0.f, c1r = 0.f;

    for (int step = 0; step < Sk; step++) {
        const int p = step & 1;

        // ---------------- phase A: layer-0 gates (k=512, split 2x256) ----------
        if (t < 256) {
            const int n = t >> 3, f = t & 7;  // stage x
            xs[n * 8 + f] = __ldg(x + ((size_t)(nb_base + n) * Sk + step) * Fk + f);
        }
        {
            float acc0[4] = {0, 0, 0, 0}, acc1[4] = {0, 0, 0, 0};
            gemm_span(gh0[p][0] + kh * 256, gh0[p][1] + kh * 256,
                      &gWf0[0][midx][kh * 16][lane], &gWf0[1][midx][kh * 16][lane],
                      16, boff0, boff1, tq, acc0, acc1);
            float* sgm = sg + kh * 2112 + mi * 528;
            const int ncol = ni * 16 + tq * 2;
            sgm[g8 * 33 + ncol + 0] = acc0[0];
            sgm[g8 * 33 + ncol + 1] = acc0[1];
            sgm[(g8 + 8) * 33 + ncol + 0] = acc0[2];
            sgm[(g8 + 8) * 33 + ncol + 1] = acc0[3];
            sgm[g8 * 33 + ncol + 8 + 0] = acc1[0];
            sgm[g8 * 33 + ncol + 8 + 1] = acc1[1];
            sgm[(g8 + 8) * 33 + ncol + 8 + 0] = acc1[2];
            sgm[(g8 + 8) * 33 + ncol + 8 + 1] = acc1[3];
        }
        __syncthreads();
        // activation layer 0: exactly one (n, dl) item per thread
        {
            float gate[4];
#pragma unroll
            for (int g = 0; g < 4; g++) {
                const int si = g * 528 + adl * 33 + an;
                float s = sg[si] + sg[2112 + si] + b0s[g * 16 + adl];
                const float* wv = wih0s + (g * 16 + adl) * 9;
                const float* xv = xs + an * 8;
#pragma unroll
                for (int f = 0; f < 8; f++) s = fmaf(xv[f], wv[f], s);
                gate[g] = s;
            }
            const float cn = sigf(gate[1]) * c0r + sigf(gate[0]) * tanh_f(gate[2]);
            c0r = cn;
            const float h = sigf(gate[3]) * tanh_f(cn);
            const size_t off = (size_t)(nb_base + an) * Hk + mt * 16 + adl;
            const __nv_bfloat16 hi = __float2bfloat16(h);
            gh0[1 - p][0][off] = hi;
            gh0[1 - p][1][off] = __float2bfloat16(h - __bfloat162float(hi));
        }
        grid_sync();  // h0_new visible

        // ------------- phase B: layer-1 gates (k=1024, kh0:h0new kh1:h1old) ----
        {
            float acc0[4] = {0, 0, 0, 0}, acc1[4] = {0, 0, 0, 0};
            const __nv_bfloat16* sH = kh ? gh1[p][0] : gh0[1 - p][0];
            const __nv_bfloat16* sL = kh ? gh1[p][1] : gh0[1 - p][1];
            gemm_span(sH, sL,
                      &gWf1[0][midx][kh * 32][lane], &gWf1[1][midx][kh * 32][lane],
                      32, boff0, boff1, tq, acc0, acc1);
            float* sgm = sg + kh * 2112 + mi * 528;
            const int ncol = ni * 16 + tq * 2;
            sgm[g8 * 33 + ncol + 0] = acc0[0];
            sgm[g8 * 33 + ncol + 1] = acc0[1];
            sgm[(g8 + 8) * 33 + ncol + 0] = acc0[2];
            sgm[(g8 + 8) * 33 + ncol + 1] = acc0[3];
            sgm[g8 * 33 + ncol + 8 + 0] = acc1[0];
            sgm[g8 * 33 + ncol + 8 + 1] = acc1[1];
            sgm[(g8 + 8) * 33 + ncol + 8 + 0] = acc1[2];
            sgm[(g8 + 8) * 33 + ncol + 8 + 1] = acc1[3];
        }
        __syncthreads();
        // activation layer 1
        {
            float gate[4];
#pragma unroll
            for (int g = 0; g < 4; g++) {
                const int si = g * 528 + adl * 33 + an;
                gate[g] = sg[si] + sg[2112 + si] + b1s[g * 16 + adl];
            }
            const float cn = sigf(gate[1]) * c1r + sigf(gate[0]) * tanh_f(gate[2]);
            c1r = cn;
            const float h = sigf(gate[3]) * tanh_f(cn);
            const size_t off = (size_t)(nb_base + an) * Hk + mt * 16 + adl;
            const __nv_bfloat16 hi = __float2bfloat16(h);
            gh1[1 - p][0][off] = hi;
            gh1[1 - p][1][off] = __float2bfloat16(h - __bfloat162float(hi));
            gh1f[1 - p][off] = h;
        }
        grid_sync();  // h1_new visible

        // ---------------- FC for this step (warps 0..7; batch row = cta) -------
        if (wid < 8) {
            const int o = wid;
            const int l = lane;
            const float* hrow = gh1f[1 - p] + (size_t)cta * Hk;
            const float* wrow = Wfc + (size_t)o * Hk;
            float s = 0.f;
#pragma unroll
            for (int j = 0; j < 16; j++) {
                const int k = l + j * 32;
                s = fmaf(__ldcg(hrow + k), __ldg(wrow + k), s);
            }
#pragma unroll
            for (int off = 16; off > 0; off >>= 1)
                s += __shfl_xor_sync(0xffffffffu, s, off);
            if (l == 0)
                out[((size_t)cta * Sk + step) * Ok + o] = s + __ldg(bfc + o);
        }
    }
}

extern "C" void kernel_launch(void* const* d_in, const int* in_sizes, int n_in,
                              void* d_out, int out_size) {
    const float* x    = (const float*)d_in[0];
    const float* Wih0 = (const float*)d_in[1];
    const float* Whh0 = (const float*)d_in[2];
    const float* bih0 = (const float*)d_in[3];
    const float* bhh0 = (const float*)d_in[4];
    const float* Wih1 = (const float*)d_in[5];
    const float* Whh1 = (const float*)d_in[6];
    const float* bih1 = (const float*)d_in[7];
    const float* bhh1 = (const float*)d_in[8];
    const float* Wfc  = (const float*)d_in[9];
    const float* bfc  = (const float*)d_in[10];
    float* out = (float*)d_out;

    lstm2_mma_kernel<<<NCTA, NTHR>>>(
        x, Wih0, Whh0, bih0, bhh0, Wih1, Whh1, bih1, bhh1, Wfc, bfc, out);
}

// round 10
// speedup vs baseline: 3.4266x; 2.0501x over previous
#include <cuda_runtime.h>
#include <cuda_bf16.h>
#include <cstdint>

#define NCTA 128
#define NTHR 512
#define Bk 128
#define Sk 1024
#define Fk 8
#define Hk 512
#define Ok 8

// ---------------- persistent device state ----------------
// Fragment-packed weights: [plane][midx=mt*4+gate][kb][lane] -> uint4 (8 bf16)
__device__ uint4 gWf0[2][128][32][32];   // layer0: k=512  (4 MB)
__device__ uint4 gWf1[2][128][64][32];   // layer1: k=1024 (8 MB)
// h planes: [parity][plane hi/lo][n*512+k]
__device__ __nv_bfloat16 gh0[2][2][Bk * Hk];
__device__ __nv_bfloat16 gh1[2][2][Bk * Hk];
__device__ float gh1f[2][Bk * Hk];       // fp32 h1 for FC
__device__ unsigned g_count, g_epoch;

// ---------------- smem layout (bytes) ----------------
// staging: 2 buffers x 2 sources x (2 planes x 32 rows x 144B = 9216)
#define STG_SRC   9216
#define STG_BUF   18432
#define STG_TOTAL 36864
#define SG_OFF    STG_TOTAL                 // float sg[2][4][16][33] = 16896B
#define XS_OFF    (SG_OFF + 16896)          // float xs[32][8] = 1024B
#define WIH0_OFF  (XS_OFF + 1024)           // float wih0s[64][9] = 2304B
#define B0_OFF    (WIH0_OFF + 2304)         // float b0s[64] = 256B
#define B1_OFF    (B0_OFF + 256)            // float b1s[64] = 256B
#define SMEM_BYTES (B1_OFF + 256)

extern __shared__ char smem_raw[];

// ---------------- helpers ----------------
__device__ __forceinline__ float sigf(float x) { return __fdividef(1.0f, 1.0f + __expf(-x)); }
__device__ __forceinline__ float tanh_f(float x) { return 2.0f * sigf(2.0f * x) - 1.0f; }

__device__ __forceinline__ uint32_t smem_u32(const void* p) {
    uint32_t a;
    asm("{ .reg .u64 t; cvta.to.shared.u64 t, %1; cvt.u32.u64 %0, t; }" : "=r"(a) : "l"(p));
    return a;
}
__device__ __forceinline__ uint32_t f2bf2u(float a, float b) {
    __nv_bfloat162 v = __floats2bfloat162_rn(a, b);
    return *reinterpret_cast<uint32_t*>(&v);
}
__device__ __forceinline__ void mma16816(float* c, uint4 a, uint32_t b0, uint32_t b1) {
    asm volatile(
        "mma.sync.aligned.m16n8k16.row.col.f32.bf16.bf16.f32 "
        "{%0,%1,%2,%3}, {%4,%5,%6,%7}, {%8,%9}, {%0,%1,%2,%3};"
        : "+f"(c[0]), "+f"(c[1]), "+f"(c[2]), "+f"(c[3])
        : "r"(a.x), "r"(a.y), "r"(a.z), "r"(a.w), "r"(b0), "r"(b1));
}
__device__ __forceinline__ void ldsm_x2(uint32_t& r0, uint32_t& r1, uint32_t addr) {
    asm volatile("ldmatrix.sync.aligned.m8n8.x2.shared.b16 {%0,%1}, [%2];"
                 : "=r"(r0), "=r"(r1) : "r"(addr));
}
#define CP_ASYNC16(dst, src) \
    asm volatile("cp.async.cg.shared.global [%0], [%1], 16;" :: "r"(dst), "l"(src))
#define CP_COMMIT() asm volatile("cp.async.commit_group;" ::: "memory")

// ---------------- software grid barrier ----------------
__device__ __forceinline__ void grid_sync() {
    __syncthreads();
    if (threadIdx.x == 0) {
        __threadfence();
        unsigned e = *(volatile unsigned*)&g_epoch;
        unsigned old = atomicAdd(&g_count, 1u);
        if (old == NCTA - 1u) {
            atomicSub(&g_count, (unsigned)NCTA);
            __threadfence();
            atomicAdd(&g_epoch, 1u);
        } else {
            while (*(volatile unsigned*)&g_epoch == e) { }
            __threadfence();
        }
    }
    __syncthreads();
}

// stage both kh-sources' 64-k chunk into buffer (1 cp.async x2 per thread)
__device__ __forceinline__ void stage_pair(
    uint32_t dstbase,
    const __nv_bfloat16* __restrict__ hi0, const __nv_bfloat16* __restrict__ lo0, int kb0,
    const __nv_bfloat16* __restrict__ hi1, const __nv_bfloat16* __restrict__ lo1, int kb1,
    int nb_base, int t)
{
    const int plane = (t >> 8) & 1;
    const int row = (t >> 3) & 31;
    const int seg = t & 7;
    const uint32_t drel = plane * 4608 + row * 144 + seg * 16;
    const size_t srel = (size_t)(nb_base + row) * Hk + seg * 8;
    const __nv_bfloat16* s0 = (plane ? lo0 : hi0) + srel + kb0;
    const __nv_bfloat16* s1 = (plane ? lo1 : hi1) + srel + kb1;
    CP_ASYNC16(dstbase + drel, s0);
    CP_ASYNC16(dstbase + STG_SRC + drel, s1);
}

// ---------------- one phase GEMM: staged-B ldmatrix + batched-A LDG ----------
// All 512 threads call uniformly (staging + barriers inside).
__device__ __forceinline__ void gemm_phase(
    uint32_t sbase, int niter,
    const uint4* __restrict__ wH, const uint4* __restrict__ wL,
    const __nv_bfloat16* __restrict__ hi0, const __nv_bfloat16* __restrict__ lo0, int kb0,
    const __nv_bfloat16* __restrict__ hi1, const __nv_bfloat16* __restrict__ lo1, int kb1,
    int nb_base, int t, const uint32_t* lds_rel,
    float* acc0, float* acc1)
{
    stage_pair(sbase, hi0, lo0, kb0, hi1, lo1, kb1, nb_base, t);
    CP_COMMIT();
#pragma unroll 1
    for (int it = 0; it < niter; it++) {
        const int cur = it & 1;
        uint4 aH[4], aL[4];
#pragma unroll
        for (int s = 0; s < 4; s++) {
            aH[s] = __ldg(wH + (it * 4 + s) * 32);
            aL[s] = __ldg(wL + (it * 4 + s) * 32);
        }
        if (it + 1 < niter) {
            stage_pair(sbase + (cur ^ 1) * STG_BUF,
                       hi0, lo0, kb0 + (it + 1) * 64,
                       hi1, lo1, kb1 + (it + 1) * 64, nb_base, t);
            CP_COMMIT();
            asm volatile("cp.async.wait_group 1;" ::: "memory");
        } else {
            asm volatile("cp.async.wait_group 0;" ::: "memory");
        }
        __syncthreads();
        const uint32_t ab = sbase + cur * STG_BUF;
#pragma unroll
        for (int s = 0; s < 4; s++) {
            uint32_t bH00, bH01, bH10, bH11, bL00, bL01, bL10, bL11;
            ldsm_x2(bH00, bH01, ab + lds_rel[0] + s * 32);
            ldsm_x2(bH10, bH11, ab + lds_rel[1] + s * 32);
            ldsm_x2(bL00, bL01, ab + lds_rel[2] + s * 32);
            ldsm_x2(bL10, bL11, ab + lds_rel[3] + s * 32);
            mma16816(acc0, aH[s], bH00, bH01);
            mma16816(acc1, aH[s], bH10, bH11);
            mma16816(acc0, aH[s], bL00, bL01);
            mma16816(acc1, aH[s], bL10, bL11);
            mma16816(acc0, aL[s], bH00, bH01);
            mma16816(acc1, aL[s], bH10, bH11);
        }
        __syncthreads();
    }
}

__global__ void __launch_bounds__(NTHR, 1) lstm2_mma_kernel(
    const float* __restrict__ x,
    const float* __restrict__ Wih0, const float* __restrict__ Whh0,
    const float* __restrict__ bih0, const float* __restrict__ bhh0,
    const float* __restrict__ Wih1, const float* __restrict__ Whh1,
    const float* __restrict__ bih1, const float* __restrict__ bhh1,
    const float* __restrict__ Wfc, const float* __restrict__ bfc,
    float* __restrict__ out)
{
    float* sg    = (float*)(smem_raw + SG_OFF);
    float* xs    = (float*)(smem_raw + XS_OFF);
    float* wih0s = (float*)(smem_raw + WIH0_OFF);
    float* b0s   = (float*)(smem_raw + B0_OFF);
    float* b1s   = (float*)(smem_raw + B1_OFF);
    const uint32_t sbase = smem_u32(smem_raw);

    const int t = threadIdx.x;
    const int cta = blockIdx.x;
    const int mt = cta >> 2;        // dim block: dims mt*16 .. mt*16+15
    const int nt = cta & 3;         // batch slab: nt*32 .. nt*32+31
    const int nb_base = nt * 32;
    const int wid = t >> 5, lane = t & 31;
    const int kh = wid >> 3;        // k-half 0..1
    const int mi = (wid >> 1) & 3;  // gate 0..3
    const int ni = wid & 1;         // n half 0..1
    const int midx = mt * 4 + mi;

    // ============ pre-pass: fragment-pack weights, zero h ============
    {
        const int gt = cta * NTHR + t;
        const int NT = NCTA * NTHR;
        uint4* w0p = &gWf0[0][0][0][0];
        for (int i = gt; i < 2 * 128 * 32 * 32; i += NT) {
            const int ln = i & 31, kb = (i >> 5) & 31, mx = (i >> 10) & 127, pl = i >> 17;
            const int mtt = mx >> 2, mii = mx & 3;
            const int gg = ln >> 2, tt = ln & 3;
            uint32_t r[4];
#pragma unroll
            for (int rr = 0; rr < 4; rr++) {
                const int row = mii * 512 + mtt * 16 + gg + (rr & 1) * 8;
                const int k = kb * 16 + tt * 2 + (rr >> 1) * 8;
                float v0 = __ldg(Whh0 + (size_t)row * 512 + k);
                float v1 = __ldg(Whh0 + (size_t)row * 512 + k + 1);
                if (pl) {
                    v0 -= __bfloat162float(__float2bfloat16(v0));
                    v1 -= __bfloat162float(__float2bfloat16(v1));
                }
                r[rr] = f2bf2u(v0, v1);
            }
            w0p[i] = make_uint4(r[0], r[1], r[2], r[3]);
        }
        uint4* w1p = &gWf1[0][0][0][0];
        for (int i = gt; i < 2 * 128 * 64 * 32; i += NT) {
            const int ln = i & 31, kb = (i >> 5) & 63, mx = (i >> 11) & 127, pl = i >> 18;
            const int mtt = mx >> 2, mii = mx & 3;
            const int gg = ln >> 2, tt = ln & 3;
            const float* src = (kb < 32) ? Wih1 : Whh1;
            const int kb2 = (kb < 32) ? kb : (kb - 32);
            uint32_t r[4];
#pragma unroll
            for (int rr = 0; rr < 4; rr++) {
                const int row = mii * 512 + mtt * 16 + gg + (rr & 1) * 8;
                const int k = kb2 * 16 + tt * 2 + (rr >> 1) * 8;
                float v0 = __ldg(src + (size_t)row * 512 + k);
                float v1 = __ldg(src + (size_t)row * 512 + k + 1);
                if (pl) {
                    v0 -= __bfloat162float(__float2bfloat16(v0));
                    v1 -= __bfloat162float(__float2bfloat16(v1));
                }
                r[rr] = f2bf2u(v0, v1);
            }
            w1p[i] = make_uint4(r[0], r[1], r[2], r[3]);
        }
        const __nv_bfloat16 z = __float2bfloat16(0.0f);
        for (int i = gt; i < 2 * 2 * Bk * Hk; i += NT) {
            (&gh0[0][0][0])[i] = z;
            (&gh1[0][0][0])[i] = z;
        }
        for (int i = gt; i < 2 * Bk * Hk; i += NT) (&gh1f[0][0])[i] = 0.0f;
    }
    // per-CTA smem constants
    for (int j = t; j < 512; j += NTHR) {
        const int rl = j >> 3, f = j & 7;
        const int grow = (rl >> 4) * 512 + mt * 16 + (rl & 15);
        wih0s[rl * 9 + f] = __ldg(Wih0 + (size_t)grow * 8 + f);
    }
    if (t < 64) {
        const int grow = (t >> 4) * 512 + mt * 16 + (t & 15);
        b0s[t] = __ldg(bih0 + grow) + __ldg(bhh0 + grow);
        b1s[t] = __ldg(bih1 + grow) + __ldg(bhh1 + grow);
    }
    grid_sync();

    // ldmatrix relative addresses [pl*2+nblock] for this warp (uses lane&15)
    uint32_t lds_rel[4];
    {
        const int lrow = lane & 7, ltile = (lane >> 3) & 1;
#pragma unroll
        for (int q = 0; q < 4; q++) {
            const int pl = q >> 1, nb = q & 1;
            lds_rel[q] = (uint32_t)(kh * STG_SRC + pl * 4608 +
                                    (ni * 16 + nb * 8 + lrow) * 144 + ltile * 16);
        }
        // reorder so index matches [bH blk0, bH blk1, bL blk0, bL blk1]
        uint32_t tmp0 = lds_rel[0], tmp1 = lds_rel[1];
        lds_rel[0] = tmp0; lds_rel[1] = tmp1;  // pl=0 blocks
        // lds_rel[2], lds_rel[3] already pl=1 blocks
    }

    // activation item for this thread
    const int an = t >> 4, adl = t & 15;
    float c0r = 0.f, c1r = 0.f;

    for (int step = 0; step < Sk; step++) {
        const int p = step & 1;

        // ---------------- phase A: layer-0 gates (k=512, kh-split) -------------
        if (t < 256) {
            const int n = t >> 3, f = t & 7;  // stage x
            xs[n * 8 + f] = __ldg(x + ((size_t)(nb_base + n) * Sk + step) * Fk + f);
        }
        {
            float acc0[4] = {0, 0, 0, 0}, acc1[4] = {0, 0, 0, 0};
            gemm_phase(sbase, 4,
                       &gWf0[0][midx][kh * 16][lane], &gWf0[1][midx][kh * 16][lane],
                       gh0[p][0], gh0[p][1], 0,
                       gh0[p][0], gh0[p][1], 256,
                       nb_base, t, lds_rel, acc0, acc1);
            float* sgm = sg + kh * 2112 + mi * 528;
            const int g8 = lane >> 2, tq = lane & 3;
            const int ncol = ni * 16 + tq * 2;
            sgm[g8 * 33 + ncol + 0] = acc0[0];
            sgm[g8 * 33 + ncol + 1] = acc0[1];
            sgm[(g8 + 8) * 33 + ncol + 0] = acc0[2];
            sgm[(g8 + 8) * 33 + ncol + 1] = acc0[3];
            sgm[g8 * 33 + ncol + 8 + 0] = acc1[0];
            sgm[g8 * 33 + ncol + 8 + 1] = acc1[1];
            sgm[(g8 + 8) * 33 + ncol + 8 + 0] = acc1[2];
            sgm[(g8 + 8) * 33 + ncol + 8 + 1] = acc1[3];
        }
        __syncthreads();
        // activation layer 0: one (n, dl) item per thread
        {
            float gate[4];
#pragma unroll
            for (int g = 0; g < 4; g++) {
                const int si = g * 528 + adl * 33 + an;
                float s = sg[si] + sg[2112 + si] + b0s[g * 16 + adl];
                const float* wv = wih0s + (g * 16 + adl) * 9;
                const float* xv = xs + an * 8;
#pragma unroll
                for (int f = 0; f < 8; f++) s = fmaf(xv[f], wv[f], s);
                gate[g] = s;
            }
            const float cn = sigf(gate[1]) * c0r + sigf(gate[0]) * tanh_f(gate[2]);
            c0r = cn;
            const float h = sigf(gate[3]) * tanh_f(cn);
            const size_t off = (size_t)(nb_base + an) * Hk + mt * 16 + adl;
            const __nv_bfloat16 hi = __float2bfloat16(h);
            gh0[1 - p][0][off] = hi;
            gh0[1 - p][1][off] = __float2bfloat16(h - __bfloat162float(hi));
        }
        grid_sync();  // h0_new visible

        // ------------- phase B: layer-1 gates (k=1024, kh0:h0new kh1:h1old) ----
        {
            float acc0[4] = {0, 0, 0, 0}, acc1[4] = {0, 0, 0, 0};
            gemm_phase(sbase, 8,
                       &gWf1[0][midx][kh * 32][lane], &gWf1[1][midx][kh * 32][lane],
                       gh0[1 - p][0], gh0[1 - p][1], 0,
                       gh1[p][0], gh1[p][1], 0,
                       nb_base, t, lds_rel, acc0, acc1);
            float* sgm = sg + kh * 2112 + mi * 528;
            const int g8 = lane >> 2, tq = lane & 3;
            const int ncol = ni * 16 + tq * 2;
            sgm[g8 * 33 + ncol + 0] = acc0[0];
            sgm[g8 * 33 + ncol + 1] = acc0[1];
            sgm[(g8 + 8) * 33 + ncol + 0] = acc0[2];
            sgm[(g8 + 8) * 33 + ncol + 1] = acc0[3];
            sgm[g8 * 33 + ncol + 8 + 0] = acc1[0];
            sgm[g8 * 33 + ncol + 8 + 1] = acc1[1];
            sgm[(g8 + 8) * 33 + ncol + 8 + 0] = acc1[2];
            sgm[(g8 + 8) * 33 + ncol + 8 + 1] = acc1[3];
        }
        __syncthreads();
        // activation layer 1
        {
            float gate[4];
#pragma unroll
            for (int g = 0; g < 4; g++) {
                const int si = g * 528 + adl * 33 + an;
                gate[g] = sg[si] + sg[2112 + si] + b1s[g * 16 + adl];
            }
            const float cn = sigf(gate[1]) * c1r + sigf(gate[0]) * tanh_f(gate[2]);
            c1r = cn;
            const float h = sigf(gate[3]) * tanh_f(cn);
            const size_t off = (size_t)(nb_base + an) * Hk + mt * 16 + adl;
            const __nv_bfloat16 hi = __float2bfloat16(h);
            gh1[1 - p][0][off] = hi;
            gh1[1 - p][1][off] = __float2bfloat16(h - __bfloat162float(hi));
            gh1f[1 - p][off] = h;
        }
        grid_sync();  // h1_new visible

        // ---------------- FC for this step (warps 0..7; batch row = cta) -------
        if (wid < 8) {
            const int o = wid;
            const int l = lane;
            const float* hrow = gh1f[1 - p] + (size_t)cta * Hk;
            const float* wrow = Wfc + (size_t)o * Hk;
            float s = 0.f;
#pragma unroll
            for (int j = 0; j < 16; j++) {
                const int k = l + j * 32;
                s = fmaf(__ldcg(hrow + k), __ldg(wrow + k), s);
            }
#pragma unroll
            for (int off = 16; off > 0; off >>= 1)
                s += __shfl_xor_sync(0xffffffffu, s, off);
            if (l == 0)
                out[((size_t)cta * Sk + step) * Ok + o] = s + __ldg(bfc + o);
        }
    }
}

extern "C" void kernel_launch(void* const* d_in, const int* in_sizes, int n_in,
                              void* d_out, int out_size) {
    const float* x    = (const float*)d_in[0];
    const float* Wih0 = (const float*)d_in[1];
    const float* Whh0 = (const float*)d_in[2];
    const float* bih0 = (const float*)d_in[3];
    const float* bhh0 = (const float*)d_in[4];
    const float* Wih1 = (const float*)d_in[5];
    const float* Whh1 = (const float*)d_in[6];
    const float* bih1 = (const float*)d_in[7];
    const float* bhh1 = (const float*)d_in[8];
    const float* Wfc  = (const float*)d_in[9];
    const float* bfc  = (const float*)d_in[10];
    float* out = (float*)d_out;

    cudaFuncSetAttribute(lstm2_mma_kernel,
                         cudaFuncAttributeMaxDynamicSharedMemorySize, SMEM_BYTES);
    lstm2_mma_kernel<<<NCTA, NTHR, SMEM_BYTES>>>(
        x, Wih0, Whh0, bih0, bhh0, Wih1, Whh1, bih1, bhh1, Wfc, bfc, out);
}

// round 11
// speedup vs baseline: 3.4588x; 1.0094x over previous
#include <cuda_runtime.h>
#include <cuda_bf16.h>
#include <cstdint>

#define NCTA 128
#define NTHR 512
#define Bk 128
#define Sk 1024
#define Fk 8
#define Hk 512
#define Ok 8

// ---------------- persistent device state ----------------
// Fragment-packed weights: [plane][midx=mt*4+gate][kb][lane] -> uint4 (8 bf16)
__device__ uint4 gWf0[2][128][32][32];   // layer0: k=512  (4 MB)
__device__ uint4 gWf1[2][128][64][32];   // layer1: k=1024 (8 MB)
// h planes: [parity][plane hi/lo][n*512+k]
__device__ __nv_bfloat16 gh0[2][2][Bk * Hk];
__device__ __nv_bfloat16 gh1[2][2][Bk * Hk];
__device__ float gh1f[2][Bk * Hk];       // fp32 h1 for FC
__device__ unsigned g_cntA, g_epA, g_cntB, g_epB;

// ---------------- smem layout (bytes) ----------------
// staging: 2 buffers x [4 kh regions x 2 planes x 32 rows x 80B]
#define STG_REG   5120        // one kh region (2 planes x 32 x 80)
#define STG_BUF   20480       // 4 kh regions
#define STG_TOTAL 40960
#define SG_OFF    STG_TOTAL                 // float sg[16][16][33] = 33792B
#define XS_OFF    (SG_OFF + 33792)          // float xs[32][8] = 1024B
#define WIH0_OFF  (XS_OFF + 1024)           // float wih0s[64][9] = 2304B
#define B0_OFF    (WIH0_OFF + 2304)         // float b0s[64]
#define B1_OFF    (B0_OFF + 256)            // float b1s[64]
#define SMEM_BYTES (B1_OFF + 256)

extern __shared__ char smem_raw[];

// ---------------- helpers ----------------
__device__ __forceinline__ float sigf(float x) { return __fdividef(1.0f, 1.0f + __expf(-x)); }
__device__ __forceinline__ float tanh_f(float x) { return 2.0f * sigf(2.0f * x) - 1.0f; }

__device__ __forceinline__ uint32_t smem_u32(const void* p) {
    uint32_t a;
    asm("{ .reg .u64 t; cvta.to.shared.u64 t, %1; cvt.u32.u64 %0, t; }" : "=r"(a) : "l"(p));
    return a;
}
__device__ __forceinline__ uint32_t f2bf2u(float a, float b) {
    __nv_bfloat162 v = __floats2bfloat162_rn(a, b);
    return *reinterpret_cast<uint32_t*>(&v);
}
__device__ __forceinline__ void mma16816(float* c, uint4 a, uint32_t b0, uint32_t b1) {
    asm volatile(
        "mma.sync.aligned.m16n8k16.row.col.f32.bf16.bf16.f32 "
        "{%0,%1,%2,%3}, {%4,%5,%6,%7}, {%8,%9}, {%0,%1,%2,%3};"
        : "+f"(c[0]), "+f"(c[1]), "+f"(c[2]), "+f"(c[3])
        : "r"(a.x), "r"(a.y), "r"(a.z), "r"(a.w), "r"(b0), "r"(b1));
}
__device__ __forceinline__ void ldsm_x2(uint32_t& r0, uint32_t& r1, uint32_t addr) {
    asm volatile("ldmatrix.sync.aligned.m8n8.x2.shared.b16 {%0,%1}, [%2];"
                 : "=r"(r0), "=r"(r1) : "r"(addr));
}
#define CP_ASYNC16(dst, src) \
    asm volatile("cp.async.cg.shared.global [%0], [%1], 16;" :: "r"(dst), "l"(src))
#define CP_COMMIT() asm volatile("cp.async.commit_group;" ::: "memory")
#define CP_WAIT0()  asm volatile("cp.async.wait_group 0;" ::: "memory")

// ---------------- split grid barrier (arrive / wait) ----------------
__device__ __forceinline__ void gb_arrive(unsigned* cnt, unsigned* ep, unsigned& snap) {
    __syncthreads();
    if (threadIdx.x == 0) {
        snap = *(volatile unsigned*)ep;   // read BEFORE arriving
        __threadfence();
        unsigned old = atomicAdd(cnt, 1u);
        if (old == NCTA - 1u) {
            atomicSub(cnt, (unsigned)NCTA);
            __threadfence();
            atomicAdd(ep, 1u);
        }
    }
}
__device__ __forceinline__ void gb_wait(unsigned* ep, unsigned snap) {
    if (threadIdx.x == 0) {
        while (*(volatile unsigned*)ep == snap) { }
        __threadfence();
    }
    __syncthreads();
}

// ---------------- cooperative chunk staging ----------------
// Each iteration stages, for all 4 kh regions, 32 rows x 32 k x 2 planes.
// Thread map: t -> (khp = t>>7, plane = (t>>6)&1, row = (t>>1)&31, half = t&1).
__device__ __forceinline__ void stage_chunk(
    uint32_t dstbuf,
    const __nv_bfloat16* __restrict__ hiP, const __nv_bfloat16* __restrict__ loP,
    int kofs, int nb_base, int t)
{
    const int khp = t >> 7;
    const int pl = (t >> 6) & 1;
    const int row = (t >> 1) & 31;
    const int half = t & 1;
    const uint32_t d = dstbuf + khp * STG_REG + pl * 2560 + row * 80 + half * 32;
    const __nv_bfloat16* s = (pl ? loP : hiP)
        + (size_t)(nb_base + row) * Hk + khp * 128 + kofs + half * 16;
    CP_ASYNC16(d, s);
    CP_ASYNC16(d + 16, s + 8);
}

// ---------------- one GEMM sub-phase: 4 iters x 32k per warp ----------------
// wH/wL pre-offset to this warp's (midx, kb-base, lane); +32 uint4 per kb.
// lmbase = kh*STG_REG + (lane&7)*80 + ((lane>>3)&1)*16 (relative ldsm addr).
__device__ __forceinline__ void gemm_sub(
    uint32_t sbase,
    const uint4* __restrict__ wH, const uint4* __restrict__ wL,
    const __nv_bfloat16* __restrict__ hiP, const __nv_bfloat16* __restrict__ loP,
    int nb_base, int t, uint32_t lmbase, float (*acc)[4])
{
    stage_chunk(sbase, hiP, loP, 0, nb_base, t);
    CP_COMMIT();
    uint4 aH0 = __ldg(wH), aL0 = __ldg(wL);
    uint4 aH1 = __ldg(wH + 32), aL1 = __ldg(wL + 32);
#pragma unroll
    for (int it = 0; it < 4; it++) {
        CP_WAIT0();
        __syncthreads();                // buf(it) ready everywhere; buf(it^1) free
        if (it < 3) {
            stage_chunk(sbase + ((it & 1) ^ 1) * STG_BUF, hiP, loP,
                        (it + 1) * 32, nb_base, t);
            CP_COMMIT();
        }
        uint4 nH0, nL0, nH1, nL1;
        if (it < 3) {                   // prefetch next iter's A fragments
            nH0 = __ldg(wH + (it + 1) * 64);
            nL0 = __ldg(wL + (it + 1) * 64);
            nH1 = __ldg(wH + (it + 1) * 64 + 32);
            nL1 = __ldg(wL + (it + 1) * 64 + 32);
        }
        const uint32_t bb = sbase + (it & 1) * STG_BUF + lmbase;
#pragma unroll
        for (int ss = 0; ss < 2; ss++) {
            const uint4 aH = ss ? aH1 : aH0;
            const uint4 aL = ss ? aL1 : aL0;
#pragma unroll
            for (int nb = 0; nb < 4; nb++) {
                uint32_t h0, h1, l0, l1;
                const uint32_t ad = bb + nb * 640 + ss * 32;
                ldsm_x2(h0, h1, ad);
                ldsm_x2(l0, l1, ad + 2560);
                mma16816(acc[nb], aH, h0, h1);
                mma16816(acc[nb], aH, l0, l1);
                mma16816(acc[nb], aL, h0, h1);
            }
        }
        if (it < 3) { aH0 = nH0; aL0 = nL0; aH1 = nH1; aL1 = nL1; }
    }
}

__global__ void __launch_bounds__(NTHR, 1) lstm2_mma_kernel(
    const float* __restrict__ x,
    const float* __restrict__ Wih0, const float* __restrict__ Whh0,
    const float* __restrict__ bih0, const float* __restrict__ bhh0,
    const float* __restrict__ Wih1, const float* __restrict__ Whh1,
    const float* __restrict__ bih1, const float* __restrict__ bhh1,
    const float* __restrict__ Wfc, const float* __restrict__ bfc,
    float* __restrict__ out)
{
    float* sg    = (float*)(smem_raw + SG_OFF);
    float* xs    = (float*)(smem_raw + XS_OFF);
    float* wih0s = (float*)(smem_raw + WIH0_OFF);
    float* b0s   = (float*)(smem_raw + B0_OFF);
    float* b1s   = (float*)(smem_raw + B1_OFF);
    const uint32_t sbase = smem_u32(smem_raw);

    const int t = threadIdx.x;
    const int cta = blockIdx.x;
    const int mt = cta >> 2;        // dim block: dims mt*16 .. mt*16+15
    const int nt = cta & 3;         // batch slab: nt*32 .. nt*32+31
    const int nb_base = nt * 32;
    const int wid = t >> 5, lane = t & 31;
    const int kh = wid >> 2;        // k-split 0..3
    const int mi = wid & 3;         // gate 0..3
    const int midx = mt * 4 + mi;

    // ============ pre-pass: fragment-pack weights, zero h ============
    {
        const int gt = cta * NTHR + t;
        const int NT = NCTA * NTHR;
        uint4* w0p = &gWf0[0][0][0][0];
        for (int i = gt; i < 2 * 128 * 32 * 32; i += NT) {
            const int ln = i & 31, kb = (i >> 5) & 31, mx = (i >> 10) & 127, pl = i >> 17;
            const int mtt = mx >> 2, mii = mx & 3;
            const int gg = ln >> 2, tt = ln & 3;
            uint32_t r[4];
#pragma unroll
            for (int rr = 0; rr < 4; rr++) {
                const int row = mii * 512 + mtt * 16 + gg + (rr & 1) * 8;
                const int k = kb * 16 + tt * 2 + (rr >> 1) * 8;
                float v0 = __ldg(Whh0 + (size_t)row * 512 + k);
                float v1 = __ldg(Whh0 + (size_t)row * 512 + k + 1);
                if (pl) {
                    v0 -= __bfloat162float(__float2bfloat16(v0));
                    v1 -= __bfloat162float(__float2bfloat16(v1));
                }
                r[rr] = f2bf2u(v0, v1);
            }
            w0p[i] = make_uint4(r[0], r[1], r[2], r[3]);
        }
        uint4* w1p = &gWf1[0][0][0][0];
        for (int i = gt; i < 2 * 128 * 64 * 32; i += NT) {
            const int ln = i & 31, kb = (i >> 5) & 63, mx = (i >> 11) & 127, pl = i >> 18;
            const int mtt = mx >> 2, mii = mx & 3;
            const int gg = ln >> 2, tt = ln & 3;
            const float* src = (kb < 32) ? Wih1 : Whh1;
            const int kb2 = (kb < 32) ? kb : (kb - 32);
            uint32_t r[4];
#pragma unroll
            for (int rr = 0; rr < 4; rr++) {
                const int row = mii * 512 + mtt * 16 + gg + (rr & 1) * 8;
                const int k = kb2 * 16 + tt * 2 + (rr >> 1) * 8;
                float v0 = __ldg(src + (size_t)row * 512 + k);
                float v1 = __ldg(src + (size_t)row * 512 + k + 1);
                if (pl) {
                    v0 -= __bfloat162float(__float2bfloat16(v0));
                    v1 -= __bfloat162float(__float2bfloat16(v1));
                }
                r[rr] = f2bf2u(v0, v1);
            }
            w1p[i] = make_uint4(r[0], r[1], r[2], r[3]);
        }
        const __nv_bfloat16 z = __float2bfloat16(0.0f);
        for (int i = gt; i < 2 * 2 * Bk * Hk; i += NT) {
            (&gh0[0][0][0])[i] = z;
            (&gh1[0][0][0])[i] = z;
        }
        for (int i = gt; i < 2 * Bk * Hk; i += NT) (&gh1f[0][0])[i] = 0.0f;
    }
    // per-CTA smem constants
    for (int j = t; j < 512; j += NTHR) {
        const int rl = j >> 3, f = j & 7;
        const int grow = (rl >> 4) * 512 + mt * 16 + (rl & 15);
        wih0s[rl * 9 + f] = __ldg(Wih0 + (size_t)grow * 8 + f);
    }
    if (t < 64) {
        const int grow = (t >> 4) * 512 + mt * 16 + (t & 15);
        b0s[t] = __ldg(bih0 + grow) + __ldg(bhh0 + grow);
        b1s[t] = __ldg(bih1 + grow) + __ldg(bhh1 + grow);
    }
    unsigned snapA = 0, snapB = 0;
    gb_arrive(&g_cntA, &g_epA, snapA);
    gb_wait(&g_epA, snapA);

    // per-warp constant addressing
    const uint32_t lmbase = (uint32_t)(kh * STG_REG + (lane & 7) * 80 + ((lane >> 3) & 1) * 16);
    const uint4* pA_H  = &gWf0[0][midx][kh * 8][lane];
    const uint4* pA_L  = &gWf0[1][midx][kh * 8][lane];
    const uint4* pB1_H = &gWf1[0][midx][32 + kh * 8][lane];
    const uint4* pB1_L = &gWf1[1][midx][32 + kh * 8][lane];
    const uint4* pB2_H = &gWf1[0][midx][kh * 8][lane];
    const uint4* pB2_L = &gWf1[1][midx][kh * 8][lane];
    float* sgm = sg + (kh * 4 + mi) * 528;   // this warp's partial-sum region
    const int cr = lane >> 2, cc = (lane & 3) * 2;

    // activation item for this thread
    const int an = t >> 4, adl = t & 15;
    float c0r = 0.f, c1r = 0.f;

    for (int s = 0; s < Sk; s++) {
        const int p = s & 1;

        // ---- stage x for this step ----
        if (t < 256) {
            const int n = t >> 3, f = t & 7;
            xs[n * 8 + f] = __ldg(x + ((size_t)(nb_base + n) * Sk + s) * Fk + f);
        }

        // ================= phase A GEMM (reads gh0[p]) =================
        {
            float acc[4][4];
#pragma unroll
            for (int i = 0; i < 4; i++)
                acc[i][0] = acc[i][1] = acc[i][2] = acc[i][3] = 0.f;
            gemm_sub(sbase, pA_H, pA_L, gh0[p][0], gh0[p][1],
                     nb_base, t, lmbase, acc);
#pragma unroll
            for (int nb = 0; nb < 4; nb++) {
                sgm[cr * 33 + nb * 8 + cc + 0] = acc[nb][0];
                sgm[cr * 33 + nb * 8 + cc + 1] = acc[nb][1];
                sgm[(cr + 8) * 33 + nb * 8 + cc + 0] = acc[nb][2];
                sgm[(cr + 8) * 33 + nb * 8 + cc + 1] = acc[nb][3];
            }
        }
        __syncthreads();
        // ---- activation layer 0 ----
        {
            float gate[4];
#pragma unroll
            for (int g = 0; g < 4; g++) {
                const int si = g * 528 + adl * 33 + an;
                float ssum = sg[si] + sg[4 * 528 + si] + sg[8 * 528 + si] + sg[12 * 528 + si]
                           + b0s[g * 16 + adl];
                const float* wv = wih0s + (g * 16 + adl) * 9;
                const float* xv = xs + an * 8;
#pragma unroll
                for (int f = 0; f < 8; f++) ssum = fmaf(xv[f], wv[f], ssum);
                gate[g] = ssum;
            }
            const float cn = sigf(gate[1]) * c0r + sigf(gate[0]) * tanh_f(gate[2]);
            c0r = cn;
            const float h = sigf(gate[3]) * tanh_f(cn);
            const size_t off = (size_t)(nb_base + an) * Hk + mt * 16 + adl;
            const __nv_bfloat16 hi = __float2bfloat16(h);
            gh0[1 - p][0][off] = hi;
            gh0[1 - p][1][off] = __float2bfloat16(h - __bfloat162float(hi));
        }
        gb_arrive(&g_cntA, &g_epA, snapA);   // publish h0_new

        // ---- finish previous step: wait h1 sync, do its FC (overlapped) ----
        if (s > 0) {
            gb_wait(&g_epB, snapB);
            if (wid < 8) {
                const int o = wid;
                const float* hrow = gh1f[p] + (size_t)cta * Hk;
                const float* wrow = Wfc + (size_t)o * Hk;
                float fs = 0.f;
#pragma unroll
                for (int j = 0; j < 16; j++) {
                    const int k = lane + j * 32;
                    fs = fmaf(__ldcg(hrow + k), __ldg(wrow + k), fs);
                }
#pragma unroll
                for (int off = 16; off > 0; off >>= 1)
                    fs += __shfl_xor_sync(0xffffffffu, fs, off);
                if (lane == 0)
                    out[((size_t)cta * Sk + (s - 1)) * Ok + o] = fs + __ldg(bfc + o);
            }
        }

        // ================= phase B ==================
        float acc[4][4];
#pragma unroll
        for (int i = 0; i < 4; i++)
            acc[i][0] = acc[i][1] = acc[i][2] = acc[i][3] = 0.f;
        // B1: W_hh1 @ h1_old (independent of h0_new -> overlaps barrier A)
        gemm_sub(sbase, pB1_H, pB1_L, gh1[p][0], gh1[p][1],
                 nb_base, t, lmbase, acc);
        gb_wait(&g_epA, snapA);              // h0_new now visible
        // B2: W_ih1 @ h0_new
        gemm_sub(sbase, pB2_H, pB2_L, gh0[1 - p][0], gh0[1 - p][1],
                 nb_base, t, lmbase, acc);
#pragma unroll
        for (int nb = 0; nb < 4; nb++) {
            sgm[cr * 33 + nb * 8 + cc + 0] = acc[nb][0];
            sgm[cr * 33 + nb * 8 + cc + 1] = acc[nb][1];
            sgm[(cr + 8) * 33 + nb * 8 + cc + 0] = acc[nb][2];
            sgm[(cr + 8) * 33 + nb * 8 + cc + 1] = acc[nb][3];
        }
        __syncthreads();
        // ---- activation layer 1 ----
        {
            float gate[4];
#pragma unroll
            for (int g = 0; g < 4; g++) {
                const int si = g * 528 + adl * 33 + an;
                gate[g] = sg[si] + sg[4 * 528 + si] + sg[8 * 528 + si] + sg[12 * 528 + si]
                        + b1s[g * 16 + adl];
            }
            const float cn = sigf(gate[1]) * c1r + sigf(gate[0]) * tanh_f(gate[2]);
            c1r = cn;
            const float h = sigf(gate[3]) * tanh_f(cn);
            const size_t off = (size_t)(nb_base + an) * Hk + mt * 16 + adl;
            const __nv_bfloat16 hi = __float2bfloat16(h);
            gh1[1 - p][0][off] = hi;
            gh1[1 - p][1][off] = __float2bfloat16(h - __bfloat162float(hi));
            gh1f[1 - p][off] = h;
        }
        gb_arrive(&g_cntB, &g_epB, snapB);   // publish h1_new
    }

    // epilogue: FC for the last step
    gb_wait(&g_epB, snapB);
    if (wid < 8) {
        const int o = wid;
        const float* hrow = gh1f[Sk & 1] + (size_t)cta * Hk;
        const float* wrow = Wfc + (size_t)o * Hk;
        float fs = 0.f;
#pragma unroll
        for (int j = 0; j < 16; j++) {
            const int k = lane + j * 32;
            fs = fmaf(__ldcg(hrow + k), __ldg(wrow + k), fs);
        }
#pragma unroll
        for (int off = 16; off > 0; off >>= 1)
            fs += __shfl_xor_sync(0xffffffffu, fs, off);
        if (lane == 0)
            out[((size_t)cta * Sk + (Sk - 1)) * Ok + o] = fs + __ldg(bfc + o);
    }
}

extern "C" void kernel_launch(void* const* d_in, const int* in_sizes, int n_in,
                              void* d_out, int out_size) {
    const float* x    = (const float*)d_in[0];
    const float* Wih0 = (const float*)d_in[1];
    const float* Whh0 = (const float*)d_in[2];
    const float* bih0 = (const float*)d_in[3];
    const float* bhh0 = (const float*)d_in[4];
    const float* Wih1 = (const float*)d_in[5];
    const float* Whh1 = (const float*)d_in[6];
    const float* bih1 = (const float*)d_in[7];
    const float* bhh1 = (const float*)d_in[8];
    const float* Wfc  = (const float*)d_in[9];
    const float* bfc  = (const float*)d_in[10];
    float* out = (float*)d_out;

    cudaFuncSetAttribute(lstm2_mma_kernel,
                         cudaFuncAttributeMaxDynamicSharedMemorySize, SMEM_BYTES);
    lstm2_mma_kernel<<<NCTA, NTHR, SMEM_BYTES>>>(
        x, Wih0, Whh0, bih0, bhh0, Wih1, Whh1, bih1, bhh1, Wfc, bfc, out);
}